// round 14
// baseline (speedup 1.0000x reference)
#include <cuda_runtime.h>
#include <cuda_bf16.h>
#include <mma.h>
#include <type_traits>
#include <math.h>
#include <cstdint>

using namespace nvcuda;

// Problem constants
#define B_ 8
#define N_ 4096
#define C_ 512
#define H_ 8
#define P_ 64
#define D_ 64

// ---------------- scratch (device globals; no runtime allocation) ----------------
// NOTE: device globals must ONLY be referenced from device code (GB300 ATS
// makes host-shadow writes silently succeed into host memory otherwise).
__device__ float g_qkv[B_ * N_ * 3 * C_];      // [b, n, 1536] fp32 (only q cols written)
__device__ float g_qinv[B_ * H_ * D_];
__device__ float g_kp[B_ * H_ * P_ * D_];
__device__ float g_vp[B_ * H_ * P_ * D_];
__device__ float g_gram[B_ * C_ * C_];         // half-K partial 0; softmaxed in place
__device__ float g_gram2[B_ * C_ * C_];        // half-K partial 1
__device__ float g_projP[4 * 16 * 64 * 512];   // proj split-K partials
__device__ __nv_bfloat16 g_xh[B_ * N_ * C_],  g_xl[B_ * N_ * C_];    // x [row, 512]
__device__ __nv_bfloat16 g_wqh[3 * C_ * C_],  g_wql[3 * C_ * C_];    // w_qkv [n, 512]
__device__ __nv_bfloat16 g_wo1h[(C_/2) * C_], g_wo1l[(C_/2) * C_];   // w_o1 [n, 512]
__device__ __nv_bfloat16 g_weh[P_ * N_], g_wel[P_ * N_];             // w_e [p, 4096]
__device__ __nv_bfloat16 g_kvh[B_ * N_ * 1024], g_kvl[B_ * N_ * 1024]; // K|V bf16 [row,1024]
__device__ __nv_bfloat16 g_xsah[B_ * N_ * C_], g_xsal[B_ * N_ * C_]; // scrambled x_sa
__device__ __nv_bfloat16 g_Mh[B_ * (C_/2) * C_], g_Ml[B_ * (C_/2) * C_]; // M^T [b,j,k]

__device__ __forceinline__ void split_bf16(float x, __nv_bfloat16& h, __nv_bfloat16& l) {
    h = __float2bfloat16(x);
    l = __float2bfloat16(x - __bfloat162float(h));
}

__device__ __forceinline__ uint32_t smem_u32(const void* p) {
    uint32_t a;
    asm("{ .reg .u64 t; cvta.to.shared.u64 t, %1; cvt.u32.u64 %0, t; }" : "=r"(a) : "l"(p));
    return a;
}
__device__ __forceinline__ void cpasync16(uint32_t dst, const void* src) {
    asm volatile("cp.async.cg.shared.global [%0], [%1], 16;" :: "r"(dst), "l"(src));
}
#define CPCOMMIT() asm volatile("cp.async.commit_group;" ::: "memory")
#define CPWAIT(n)  asm volatile("cp.async.wait_group " #n ";" ::: "memory")

#define RM_STR 24
#define KM128 136

// =====================================================================
// 3-stage cp.async wmma core for ROWxROW GEMMs (A [128,K] row-major,
// B [128,K] row-major -> C = A B^T). 256 threads, 8 warps (2m x 4n).
// Unpadded stage tiles (stride 16 elems), 16KB/stage x 3 = 48KB static.
// ONE __syncthreads per 16-k chunk (stage written at kt+2 is 2 behind reads).
// =====================================================================
typedef __nv_bfloat16 bf16;

__device__ __forceinline__ void gemm_rr3(
    const bf16* __restrict__ Ah, const bf16* __restrict__ Al, int lda,
    const bf16* __restrict__ Bh, const bf16* __restrict__ Bl, int ldb,
    int K, wmma::fragment<wmma::accumulator, 16, 16, 16, float> (&acc)[4][2],
    bf16 (*sbuf)[4][2048]) {                  // sbuf[3][4][2048]: Ah,Al,Bh,Bl
    int tid = threadIdx.x;
    int wid = tid >> 5;
    int wm = wid & 1, wn = wid >> 1;
    int row = tid >> 1, q = tid & 1;          // 128 rows x 2 halves (8 elems)
    int so = (row * 16 + q * 8) * 2;          // byte offset within a 4KB tile

    auto PF = [&](int kc, int st) {
        int k0 = kc << 4;
        uint32_t base = smem_u32(sbuf[st]);
        size_t oa = (size_t)row * lda + k0 + q * 8;
        size_t ob = (size_t)row * ldb + k0 + q * 8;
        cpasync16(base + so,         Ah + oa);
        cpasync16(base + 4096 + so,  Al + oa);
        cpasync16(base + 8192 + so,  Bh + ob);
        cpasync16(base + 12288 + so, Bl + ob);
        CPCOMMIT();
    };

#pragma unroll
    for (int i = 0; i < 4; i++)
#pragma unroll
        for (int j = 0; j < 2; j++) wmma::fill_fragment(acc[i][j], 0.0f);

    int nk = K >> 4;
    PF(0, 0);
    if (nk > 1) PF(1, 1);
    for (int kt = 0; kt < nk; kt++) {
        int st = kt - (kt / 3) * 3;           // kt % 3
        if (kt + 1 < nk) { CPWAIT(1); } else { CPWAIT(0); }
        __syncthreads();                      // stage kt visible; stage (kt+2)%3 free
        if (kt + 2 < nk) PF(kt + 2, (kt + 2) - ((kt + 2) / 3) * 3);
        const bf16* pAh = sbuf[st][0];
        const bf16* pAl = sbuf[st][1];
        const bf16* pBh = sbuf[st][2];
        const bf16* pBl = sbuf[st][3];
        wmma::fragment<wmma::matrix_a, 16, 16, 16, bf16, wmma::row_major> ah[4], al[4];
        wmma::fragment<wmma::matrix_b, 16, 16, 16, bf16, wmma::col_major> bh[2], bl[2];
#pragma unroll
        for (int i = 0; i < 4; i++) {
            int m = wm * 64 + i * 16;
            wmma::load_matrix_sync(ah[i], pAh + m * 16, 16);
            wmma::load_matrix_sync(al[i], pAl + m * 16, 16);
        }
#pragma unroll
        for (int j = 0; j < 2; j++) {
            int n = wn * 32 + j * 16;
            wmma::load_matrix_sync(bh[j], pBh + n * 16, 16);
            wmma::load_matrix_sync(bl[j], pBl + n * 16, 16);
        }
#pragma unroll
        for (int i = 0; i < 4; i++)
#pragma unroll
            for (int j = 0; j < 2; j++) {
                wmma::mma_sync(acc[i][j], ah[i], bh[j], acc[i][j]);
                wmma::mma_sync(acc[i][j], ah[i], bl[j], acc[i][j]);
                wmma::mma_sync(acc[i][j], al[i], bh[j], acc[i][j]);
            }
    }
}

// ================= K1: qkv — q tiles -> fp32 g_qkv; K/V tiles -> bf16 split =====
__global__ __launch_bounds__(256) void k_qkv_w() {
    __shared__ bf16 sbuf[3][4][2048];
    int tid = threadIdx.x;
    int wid = tid >> 5, lane = tid & 31;
    int wm = wid & 1, wn = wid >> 1;
    int m0 = blockIdx.y * 128, n0 = blockIdx.x * 128;
    wmma::fragment<wmma::accumulator, 16, 16, 16, float> acc[4][2];
    gemm_rr3(g_xh + (size_t)m0 * 512, g_xl + (size_t)m0 * 512, 512,
             g_wqh + (size_t)n0 * 512, g_wql + (size_t)n0 * 512, 512, 512, acc, sbuf);
    if (n0 < 512) {   // q columns: fp32 to g_qkv
#pragma unroll
        for (int i = 0; i < 4; i++)
#pragma unroll
            for (int j = 0; j < 2; j++) {
                int m = wm * 64 + i * 16, n = wn * 32 + j * 16;
                wmma::store_matrix_sync(g_qkv + (size_t)(m0 + m) * 1536 + n0 + n,
                                        acc[i][j], 1536, wmma::mem_row_major);
            }
    } else {          // K/V columns: bf16 hi/lo split via per-warp smem relay
        __syncthreads();   // all stage reads done; reuse sbuf as fp32 scratch
        float* cbuf = reinterpret_cast<float*>(sbuf) + wid * 256;
#pragma unroll
        for (int i = 0; i < 4; i++)
#pragma unroll
            for (int j = 0; j < 2; j++) {
                wmma::store_matrix_sync(cbuf, acc[i][j], 16, wmma::mem_row_major);
                __syncwarp();
                int mrow = m0 + wm * 64 + i * 16;
                int col0 = n0 - 512 + wn * 32 + j * 16;
#pragma unroll
                for (int e = lane; e < 256; e += 32) {
                    int r = e >> 4, c = e & 15;
                    bf16 hh, ll;
                    split_bf16(cbuf[e], hh, ll);
                    size_t o = (size_t)(mrow + r) * 1024 + col0 + c;
                    g_kvh[o] = hh;
                    g_kvl[o] = ll;
                }
                __syncwarp();
            }
    }
}

// ================= K8: out[:, :256] = xsa @ w_o1^T =================
__global__ __launch_bounds__(256) void k_out1_w(float* __restrict__ out) {
    __shared__ bf16 sbuf[3][4][2048];
    int wid = threadIdx.x >> 5;
    int wm = wid & 1, wn = wid >> 1;
    int m0 = blockIdx.y * 128, n0 = blockIdx.x * 128;
    wmma::fragment<wmma::accumulator, 16, 16, 16, float> acc[4][2];
    gemm_rr3(g_xsah + (size_t)m0 * 512, g_xsal + (size_t)m0 * 512, 512,
             g_wo1h + (size_t)n0 * 512, g_wo1l + (size_t)n0 * 512, 512, 512, acc, sbuf);
#pragma unroll
    for (int i = 0; i < 4; i++)
#pragma unroll
        for (int j = 0; j < 2; j++) {
            int m = wm * 64 + i * 16, n = wn * 32 + j * 16;
            wmma::store_matrix_sync(out + (size_t)(m0 + m) * 512 + n0 + n,
                                    acc[i][j], 512, wmma::mem_row_major);
        }
}

// ================= K9: out[:, 256:] = x @ M[b] =================
__global__ __launch_bounds__(256) void k_out2_w(float* __restrict__ out) {
    __shared__ bf16 sbuf[3][4][2048];
    int wid = threadIdx.x >> 5;
    int wm = wid & 1, wn = wid >> 1;
    int m0 = blockIdx.y * 128, n0 = blockIdx.x * 128;
    int b = m0 >> 12;
    wmma::fragment<wmma::accumulator, 16, 16, 16, float> acc[4][2];
    gemm_rr3(g_xh + (size_t)m0 * 512, g_xl + (size_t)m0 * 512, 512,
             g_Mh + ((size_t)b * 256 + n0) * 512, g_Ml + ((size_t)b * 256 + n0) * 512,
             512, 512, acc, sbuf);
#pragma unroll
    for (int i = 0; i < 4; i++)
#pragma unroll
        for (int j = 0; j < 2; j++) {
            int m = wm * 64 + i * 16, n = wn * 32 + j * 16;
            wmma::store_matrix_sync(out + (size_t)(m0 + m) * 512 + 256 + n0 + n,
                                    acc[i][j], 512, wmma::mem_row_major);
        }
}

// =====================================================================
// 2-stage padded core (round-12 proven) — kept for gram (k-major tiles).
// =====================================================================
template <bool ACol, bool BCol>
__device__ __forceinline__ void gemm_wmma4(
    const bf16* __restrict__ Ah, const bf16* __restrict__ Al, int lda,
    const bf16* __restrict__ Bh, const bf16* __restrict__ Bl, int ldb,
    int K, float* __restrict__ Cp, int ldc) {
    using ALay = typename std::conditional<ACol, wmma::col_major, wmma::row_major>::type;
    using BLay = typename std::conditional<BCol, wmma::col_major, wmma::row_major>::type;
    constexpr int ASZ = ACol ? 16 * KM128 : 128 * RM_STR;
    constexpr int BSZ = BCol ? 128 * RM_STR : 16 * KM128;
    __shared__ bf16 sAh[2][ASZ], sAl[2][ASZ];
    __shared__ bf16 sBh[2][BSZ], sBl[2][BSZ];

    int tid = threadIdx.x;
    int wid = tid >> 5;
    int wm = wid & 1, wn = wid >> 1;

    auto PF = [&](int kc, int st) {
        int k0 = kc << 4;
        uint32_t ah = smem_u32(sAh[st]), al = smem_u32(sAl[st]);
        uint32_t bhs = smem_u32(sBh[st]), bls = smem_u32(sBl[st]);
        {
            size_t o; int so;
            if (ACol) { int kr = tid >> 4, q = tid & 15;
                        o = (size_t)(k0 + kr) * lda + q * 8; so = kr * KM128 + q * 8; }
            else      { int row = tid >> 1, q = tid & 1;
                        o = (size_t)row * lda + k0 + q * 8; so = row * RM_STR + q * 8; }
            cpasync16(ah + so * 2, Ah + o);
            cpasync16(al + so * 2, Al + o);
        }
        {
            size_t o; int so;
            if (BCol) { int row = tid >> 1, q = tid & 1;
                        o = (size_t)row * ldb + k0 + q * 8; so = row * RM_STR + q * 8; }
            else      { int kr = tid >> 4, q = tid & 15;
                        o = (size_t)(k0 + kr) * ldb + q * 8; so = kr * KM128 + q * 8; }
            cpasync16(bhs + so * 2, Bh + o);
            cpasync16(bls + so * 2, Bl + o);
        }
        CPCOMMIT();
    };

    wmma::fragment<wmma::accumulator, 16, 16, 16, float> acc[4][2];
#pragma unroll
    for (int i = 0; i < 4; i++)
#pragma unroll
        for (int j = 0; j < 2; j++) wmma::fill_fragment(acc[i][j], 0.0f);

    int nk = K >> 4;
    PF(0, 0);
    for (int kt = 0; kt < nk; kt++) {
        int st = kt & 1;
        if (kt + 1 < nk) { PF(kt + 1, st ^ 1); CPWAIT(1); }
        else             { CPWAIT(0); }
        __syncthreads();
        wmma::fragment<wmma::matrix_a, 16, 16, 16, bf16, ALay> ah[4], al[4];
        wmma::fragment<wmma::matrix_b, 16, 16, 16, bf16, BLay> bh[2], bl[2];
#pragma unroll
        for (int i = 0; i < 4; i++) {
            int m = wm * 64 + i * 16;
            if (ACol) {
                wmma::load_matrix_sync(ah[i], sAh[st] + m, KM128);
                wmma::load_matrix_sync(al[i], sAl[st] + m, KM128);
            } else {
                wmma::load_matrix_sync(ah[i], sAh[st] + m * RM_STR, RM_STR);
                wmma::load_matrix_sync(al[i], sAl[st] + m * RM_STR, RM_STR);
            }
        }
#pragma unroll
        for (int j = 0; j < 2; j++) {
            int n = wn * 32 + j * 16;
            if (BCol) {
                wmma::load_matrix_sync(bh[j], sBh[st] + n * RM_STR, RM_STR);
                wmma::load_matrix_sync(bl[j], sBl[st] + n * RM_STR, RM_STR);
            } else {
                wmma::load_matrix_sync(bh[j], sBh[st] + n, KM128);
                wmma::load_matrix_sync(bl[j], sBl[st] + n, KM128);
            }
        }
#pragma unroll
        for (int i = 0; i < 4; i++)
#pragma unroll
            for (int j = 0; j < 2; j++) {
                wmma::mma_sync(acc[i][j], ah[i], bh[j], acc[i][j]);
                wmma::mma_sync(acc[i][j], ah[i], bl[j], acc[i][j]);
                wmma::mma_sync(acc[i][j], al[i], bh[j], acc[i][j]);
            }
        __syncthreads();
    }
#pragma unroll
    for (int i = 0; i < 4; i++)
#pragma unroll
        for (int j = 0; j < 2; j++) {
            int m = wm * 64 + i * 16, n = wn * 32 + j * 16;
            wmma::store_matrix_sync(Cp + (size_t)m * ldc + n, acc[i][j], ldc,
                                    wmma::mem_row_major);
        }
}

// ================= K4: Gram[b] = X^T X, split-K=2 =================
__global__ __launch_bounds__(256) void k_gram_w() {
    int b = blockIdx.z >> 1, half = blockIdx.z & 1;
    int c10 = blockIdx.y * 128, c20 = blockIdx.x * 128;
    const bf16* xh = g_xh + (size_t)b * N_ * C_ + (size_t)half * 2048 * 512;
    const bf16* xl = g_xl + (size_t)b * N_ * C_ + (size_t)half * 2048 * 512;
    float* dst = (half ? g_gram2 : g_gram) + ((size_t)(b * 512 + c10)) * 512 + c20;
    gemm_wmma4<true, false>(xh + c10, xl + c10, 512, xh + c20, xl + c20, 512,
                            2048, dst, 512);
}

// ================= K3a: proj partials = w_e @ KV, 64x128 tiles, split-K=4 ======
__global__ __launch_bounds__(128) void k_proj_n() {
    __shared__ bf16 sAh[2][64 * RM_STR], sAl[2][64 * RM_STR];
    __shared__ bf16 sBh[2][16 * KM128], sBl[2][16 * KM128];
    int tid = threadIdx.x;
    int wn = tid >> 5;
    int n0 = blockIdx.x * 128;
    int s = blockIdx.y;          // slab b*2+kv
    int b = s >> 1, kv = s & 1;
    int ks = blockIdx.z;
    const bf16* Ah = g_weh + ks * 1024;
    const bf16* Al = g_wel + ks * 1024;
    const bf16* Bh = g_kvh + (size_t)b * N_ * 1024 + (size_t)ks * 1024 * 1024 + kv * 512 + n0;
    const bf16* Bl = g_kvl + (size_t)b * N_ * 1024 + (size_t)ks * 1024 * 1024 + kv * 512 + n0;

    auto PF = [&](int kc, int st) {
        int k0 = kc << 4;
        uint32_t ah = smem_u32(sAh[st]), al = smem_u32(sAl[st]);
        uint32_t bhs = smem_u32(sBh[st]), bls = smem_u32(sBl[st]);
        {
            int row = tid >> 1, q = tid & 1;
            size_t o = (size_t)row * N_ + k0 + q * 8;
            int so = row * RM_STR + q * 8;
            cpasync16(ah + so * 2, Ah + o);
            cpasync16(al + so * 2, Al + o);
        }
#pragma unroll
        for (int u = 0; u < 2; u++) {
            int idx = u * 128 + tid;
            int kr = idx >> 4, q = idx & 15;
            size_t o = (size_t)(k0 + kr) * 1024 + q * 8;
            int so = kr * KM128 + q * 8;
            cpasync16(bhs + so * 2, Bh + o);
            cpasync16(bls + so * 2, Bl + o);
        }
        CPCOMMIT();
    };

    wmma::fragment<wmma::accumulator, 16, 16, 16, float> acc[4][2];
#pragma unroll
    for (int i = 0; i < 4; i++)
#pragma unroll
        for (int j = 0; j < 2; j++) wmma::fill_fragment(acc[i][j], 0.0f);

    PF(0, 0);
    for (int kt = 0; kt < 64; kt++) {    // K=1024
        int st = kt & 1;
        if (kt + 1 < 64) { PF(kt + 1, st ^ 1); CPWAIT(1); }
        else             { CPWAIT(0); }
        __syncthreads();
        wmma::fragment<wmma::matrix_a, 16, 16, 16, bf16, wmma::row_major> ah[4], al[4];
        wmma::fragment<wmma::matrix_b, 16, 16, 16, bf16, wmma::row_major> bh[2], bl[2];
#pragma unroll
        for (int i = 0; i < 4; i++) {
            wmma::load_matrix_sync(ah[i], sAh[st] + i * 16 * RM_STR, RM_STR);
            wmma::load_matrix_sync(al[i], sAl[st] + i * 16 * RM_STR, RM_STR);
        }
#pragma unroll
        for (int j = 0; j < 2; j++) {
            int n = wn * 32 + j * 16;
            wmma::load_matrix_sync(bh[j], sBh[st] + n, KM128);
            wmma::load_matrix_sync(bl[j], sBl[st] + n, KM128);
        }
#pragma unroll
        for (int i = 0; i < 4; i++)
#pragma unroll
            for (int j = 0; j < 2; j++) {
                wmma::mma_sync(acc[i][j], ah[i], bh[j], acc[i][j]);
                wmma::mma_sync(acc[i][j], ah[i], bl[j], acc[i][j]);
                wmma::mma_sync(acc[i][j], al[i], bh[j], acc[i][j]);
            }
        __syncthreads();
    }
    float* Cp = g_projP + (((size_t)ks * 16 + s) * 64) * 512 + n0;
#pragma unroll
    for (int i = 0; i < 4; i++)
#pragma unroll
        for (int j = 0; j < 2; j++)
            wmma::store_matrix_sync(Cp + (size_t)(i * 16) * 512 + wn * 32 + j * 16,
                                    acc[i][j], 512, wmma::mem_row_major);
}

// ================= K3b: reduce proj partials + b_e -> g_kp/g_vp ================
__global__ __launch_bounds__(256) void k_proj_red(const float* __restrict__ b_e) {
    int s = blockIdx.y;
    int e0 = (blockIdx.x * 256 + threadIdx.x) * 4;
    int p = e0 >> 9, d = e0 & 511;
    float4 acc = make_float4(0.f, 0.f, 0.f, 0.f);
#pragma unroll
    for (int ks = 0; ks < 4; ks++) {
        float4 v = *(const float4*)(g_projP + (((size_t)ks * 16 + s) * 64 + p) * 512 + d);
        acc.x += v.x; acc.y += v.y; acc.z += v.z; acc.w += v.w;
    }
    float be = b_e[p];
    acc.x += be; acc.y += be; acc.z += be; acc.w += be;
    int b = s >> 1, kv = s & 1, h = d >> 6, dd = d & 63;
    float* dst = (kv ? g_vp : g_kp) + (((size_t)(b * 8 + h) * 64 + p) * 64 + dd);
    *(float4*)dst = acc;
}

// ================= bias epilogue: out[r][c] += b_o1/b_o2 =================
__global__ __launch_bounds__(256) void k_bias(const float* __restrict__ b_o1,
                                              const float* __restrict__ b_o2,
                                              float* __restrict__ out) {
    size_t i = ((size_t)blockIdx.x * 256 + threadIdx.x) * 4;
    int c = (int)(i & 511);
    const float* bias = (c < 256) ? (b_o1 + c) : (b_o2 + c - 256);
    float4 v = *(float4*)(out + i);
    float4 bb = *(const float4*)bias;
    v.x += bb.x; v.y += bb.y; v.z += bb.z; v.w += bb.w;
    *(float4*)(out + i) = v;
}

// ================= conversions (destinations referenced in DEVICE code) =====
__device__ __forceinline__ void split4_to(const float* __restrict__ s,
                                          bf16* __restrict__ h,
                                          bf16* __restrict__ l, size_t i) {
    float4 v = *(const float4*)(s + i);
    bf16 hh[4], ll[4];
    split_bf16(v.x, hh[0], ll[0]); split_bf16(v.y, hh[1], ll[1]);
    split_bf16(v.z, hh[2], ll[2]); split_bf16(v.w, hh[3], ll[3]);
    *(uint2*)(h + i) = *(uint2*)hh;
    *(uint2*)(l + i) = *(uint2*)ll;
}

__global__ void c_split_x(const float* __restrict__ s) {
    size_t i = ((size_t)blockIdx.x * 256 + threadIdx.x) * 4;
    split4_to(s, g_xh, g_xl, i);
}
__global__ void c_split_wq(const float* __restrict__ s) {
    size_t i = ((size_t)blockIdx.x * 256 + threadIdx.x) * 4;
    split4_to(s, g_wqh, g_wql, i);
}
__global__ void c_split_wo1(const float* __restrict__ s) {
    size_t i = ((size_t)blockIdx.x * 256 + threadIdx.x) * 4;
    split4_to(s, g_wo1h, g_wo1l, i);
}
__global__ void c_split_we(const float* __restrict__ s) {
    size_t i = ((size_t)blockIdx.x * 256 + threadIdx.x) * 4;
    split4_to(s, g_weh, g_wel, i);
}

// ================= K2: q token-axis L2 norm inverses (coalesced) =============
__global__ __launch_bounds__(256) void k_qnorm() {
    int bh = blockIdx.x;
    int b = bh >> 3, h = bh & 7;
    int tid = threadIdx.x;
    int rg = tid >> 4;
    int q4 = tid & 15;
    const float* base = g_qkv + (size_t)b * (N_ * 1536) + h * 64 + q4 * 4;
    float4 s = make_float4(0.f, 0.f, 0.f, 0.f);
    for (int n = rg; n < N_; n += 16) {
        float4 v = *(const float4*)(base + (size_t)n * 1536);
        s.x += v.x * v.x; s.y += v.y * v.y; s.z += v.z * v.z; s.w += v.w * v.w;
    }
    __shared__ float4 red[16][16];
    red[rg][q4] = s;
    __syncthreads();
    if (tid < 16) {
        float4 tot = red[0][tid];
#pragma unroll
        for (int r = 1; r < 16; r++) {
            float4 v = red[r][tid];
            tot.x += v.x; tot.y += v.y; tot.z += v.z; tot.w += v.w;
        }
        float* dst = g_qinv + bh * 64 + tid * 4;
        dst[0] = 1.f / fmaxf(sqrtf(tot.x), 1e-12f);
        dst[1] = 1.f / fmaxf(sqrtf(tot.y), 1e-12f);
        dst[2] = 1.f / fmaxf(sqrtf(tot.z), 1e-12f);
        dst[3] = 1.f / fmaxf(sqrtf(tot.w), 1e-12f);
    }
}

// ================= K5: row softmax of (gram+gram2) * temperature =============
__global__ __launch_bounds__(256) void k_softmax512(const float* __restrict__ temp) {
    int row = blockIdx.x;
    float t = temp[0];
    float* p = g_gram + (size_t)row * 512;
    const float* p2 = g_gram2 + (size_t)row * 512;
    int tid = threadIdx.x;
    __shared__ float red[256];
    float v0 = (p[tid] + p2[tid]) * t;
    float v1 = (p[tid + 256] + p2[tid + 256]) * t;
    red[tid] = fmaxf(v0, v1);
    __syncthreads();
    for (int s = 128; s > 0; s >>= 1) {
        if (tid < s) red[tid] = fmaxf(red[tid], red[tid + s]);
        __syncthreads();
    }
    float mx = red[0];
    __syncthreads();
    float e0 = __expf(v0 - mx), e1 = __expf(v1 - mx);
    red[tid] = e0 + e1;
    __syncthreads();
    for (int s = 128; s > 0; s >>= 1) {
        if (tid < s) red[tid] += red[tid + s];
        __syncthreads();
    }
    float inv = 1.f / red[0];
    p[tid] = e0 * inv;
    p[tid + 256] = e1 * inv;
}

// ================= K6: fused spatial attention (writes bf16 hi/lo) =================
__global__ __launch_bounds__(128) void k_sa(const float* __restrict__ temp2) {
    __shared__ float kp_s[P_ * D_];
    __shared__ float vp_s[P_ * D_];
    __shared__ float qi_s[D_];
    int bh = blockIdx.y;
    int b = bh >> 3, h = bh & 7;
    int n = blockIdx.x * 128 + threadIdx.x;
    const float4* kp4 = (const float4*)(g_kp + bh * (P_ * D_));
    const float4* vp4 = (const float4*)(g_vp + bh * (P_ * D_));
    for (int i = threadIdx.x; i < (P_ * D_) / 4; i += 128) {
        ((float4*)kp_s)[i] = kp4[i];
        ((float4*)vp_s)[i] = vp4[i];
    }
    if (threadIdx.x < 64) qi_s[threadIdx.x] = g_qinv[bh * 64 + threadIdx.x];
    __syncthreads();
    float t2 = temp2[h];
    const float* qrow = g_qkv + (size_t)b * (N_ * 1536) + (size_t)n * 1536 + h * 64;

    float q[64];
#pragma unroll
    for (int d = 0; d < 64; d++) q[d] = qrow[d] * qi_s[d];

    float s[64];
    float mx = -1e30f;
#pragma unroll
    for (int p = 0; p < 64; p++) {
        float acc = 0.f;
#pragma unroll
        for (int d = 0; d < 64; d += 4) {
            float4 k4 = *(const float4*)&kp_s[p * 64 + d];
            acc += q[d] * k4.x + q[d + 1] * k4.y + q[d + 2] * k4.z + q[d + 3] * k4.w;
        }
        s[p] = acc * t2;
        mx = fmaxf(mx, s[p]);
    }
    float sum = 0.f;
#pragma unroll
    for (int p = 0; p < 64; p++) {
        s[p] = __expf(s[p] - mx);
        sum += s[p];
    }
    float inv = 1.f / sum;

    float o[64];
#pragma unroll
    for (int d = 0; d < 64; d++) o[d] = 0.f;
#pragma unroll
    for (int p = 0; p < 64; p++) {
        float sp = s[p] * inv;
#pragma unroll
        for (int d = 0; d < 64; d += 4) {
            float4 v4 = *(const float4*)&vp_s[p * 64 + d];
            o[d] += sp * v4.x;
            o[d + 1] += sp * v4.y;
            o[d + 2] += sp * v4.z;
            o[d + 3] += sp * v4.w;
        }
    }
    int rbase = h * 8 + (n >> 9);
    int col = n & 511;
    size_t boff = (size_t)b * (N_ * C_);
#pragma unroll
    for (int d = 0; d < 64; d++) {
        bf16 hh, ll;
        split_bf16(o[d], hh, ll);
        size_t idx = boff + (size_t)(d * 64 + rbase) * 512 + col;
        g_xsah[idx] = hh;
        g_xsal[idx] = ll;
    }
}

// ================= K7: M^T[b,j,k] = (attn^T @ w_o2^T)^T, bf16 hi/lo out =================
#define SP2 132
__device__ __forceinline__ void gemmM(
    const float* __restrict__ A, int lda, const float* __restrict__ B, int ldb,
    int K, float (&acc)[8][8], float (*As)[8][SP2], float (*Bs)[8][SP2]) {
    int tid = threadIdx.x;
    int tx = tid & 15, ty = tid >> 4;
    int rowT = tid >> 1, kqT = (tid & 1) * 4;
    int krD = tid >> 5, mqD = (tid & 31) * 4;
    float4 ra, rb;
    auto loadA = [&](int k0) { ra = *(const float4*)&A[(size_t)(k0 + krD) * lda + mqD]; };
    auto loadB = [&](int k0) { rb = *(const float4*)&B[(size_t)rowT * ldb + k0 + kqT]; };
    auto storeA = [&](int buf) { *(float4*)&As[buf][krD][mqD] = ra; };
    auto storeB = [&](int buf) {
        Bs[buf][kqT + 0][rowT] = rb.x; Bs[buf][kqT + 1][rowT] = rb.y;
        Bs[buf][kqT + 2][rowT] = rb.z; Bs[buf][kqT + 3][rowT] = rb.w;
    };
    loadA(0); loadB(0); storeA(0); storeB(0);
    __syncthreads();
    int nk = K >> 3;
    for (int kt = 0; kt < nk; kt++) {
        int cur = kt & 1;
        if (kt + 1 < nk) { loadA((kt + 1) << 3); loadB((kt + 1) << 3); }
#pragma unroll
        for (int kk = 0; kk < 8; kk++) {
            float4 a0 = *(const float4*)&As[cur][kk][ty * 8];
            float4 a1 = *(const float4*)&As[cur][kk][ty * 8 + 4];
            float4 b0 = *(const float4*)&Bs[cur][kk][tx * 8];
            float4 b1 = *(const float4*)&Bs[cur][kk][tx * 8 + 4];
            float a[8] = {a0.x, a0.y, a0.z, a0.w, a1.x, a1.y, a1.z, a1.w};
            float b[8] = {b0.x, b0.y, b0.z, b0.w, b1.x, b1.y, b1.z, b1.w};
#pragma unroll
            for (int i = 0; i < 8; i++)
#pragma unroll
                for (int j = 0; j < 8; j++) acc[i][j] += a[i] * b[j];
        }
        if (kt + 1 < nk) { storeA(cur ^ 1); storeB(cur ^ 1); __syncthreads(); }
    }
}

__global__ __launch_bounds__(256) void k_M(const float* __restrict__ w_o2) {
    __shared__ float As[2][8][SP2];
    __shared__ float Bs[2][8][SP2];
    int b = blockIdx.z;
    int m0 = blockIdx.y * 128;
    int n0 = blockIdx.x * 128;
    const float* A = g_gram + (size_t)b * (512 * 512);
    float acc[8][8] = {};
    gemmM(A + m0, 512, w_o2 + (size_t)n0 * 512, 512, 512, acc, As, Bs);
    int tx = threadIdx.x & 15, ty = threadIdx.x >> 4;
#pragma unroll
    for (int i = 0; i < 8; i++) {
        int k = m0 + ty * 8 + i;
#pragma unroll
        for (int jj = 0; jj < 8; jj++) {
            int j = n0 + tx * 8 + jj;
            bf16 hh, ll;
            split_bf16(acc[i][jj], hh, ll);
            size_t idx = ((size_t)b * 256 + j) * 512 + k;
            g_Mh[idx] = hh;
            g_Ml[idx] = ll;
        }
    }
}

// ================= launch =================
extern "C" void kernel_launch(void* const* d_in, const int* in_sizes, int n_in,
                              void* d_out, int out_size) {
    const float* x      = (const float*)d_in[0];
    const float* w_qkv  = (const float*)d_in[1];
    const float* w_e    = (const float*)d_in[2];
    const float* b_e    = (const float*)d_in[3];
    const float* temp   = (const float*)d_in[4];
    const float* temp2  = (const float*)d_in[5];
    const float* w_o1   = (const float*)d_in[6];
    const float* b_o1   = (const float*)d_in[7];
    const float* w_o2   = (const float*)d_in[8];
    const float* b_o2   = (const float*)d_in[9];
    float* out = (float*)d_out;

    // bf16 hi/lo conversions (globals referenced inside kernels only)
    c_split_x<<<(B_ * N_ * C_) / 1024, 256>>>(x);
    c_split_wq<<<(3 * C_ * C_) / 1024, 256>>>(w_qkv);
    c_split_wo1<<<((C_ / 2) * C_) / 1024, 256>>>(w_o1);
    c_split_we<<<(P_ * N_) / 1024, 256>>>(w_e);

    k_qkv_w<<<dim3(12, 256), 256>>>();            // 3-stage core: q->fp32, K/V->bf16
    k_qnorm<<<64, 256>>>();
    k_proj_n<<<dim3(4, 16, 4), 128>>>();          // split-K=4 partials
    k_proj_red<<<dim3(32, 16), 256>>>(b_e);
    k_gram_w<<<dim3(4, 4, 16), 256>>>();          // split-K=2
    k_softmax512<<<B_ * C_, 256>>>(temp);
    k_sa<<<dim3(32, 64), 128>>>(temp2);
    k_M<<<dim3(2, 4, 8), 256>>>(w_o2);
    k_out1_w<<<dim3(2, 256), 256>>>(out);         // 3-stage core
    k_out2_w<<<dim3(2, 256), 256>>>(out);         // 3-stage core
    k_bias<<<(B_ * N_ * C_) / 1024, 256>>>(b_o1, b_o2, out);
}

// round 15
// speedup vs baseline: 1.0428x; 1.0428x over previous
#include <cuda_runtime.h>
#include <cuda_bf16.h>
#include <mma.h>
#include <type_traits>
#include <math.h>
#include <cstdint>

using namespace nvcuda;

// Problem constants
#define B_ 8
#define N_ 4096
#define C_ 512
#define H_ 8
#define P_ 64
#define D_ 64

// ---------------- scratch (device globals; no runtime allocation) ----------------
// NOTE: device globals must ONLY be referenced from device code (GB300 ATS
// makes host-shadow writes silently succeed into host memory otherwise).
__device__ float g_qkv[B_ * N_ * 3 * C_];      // [b, n, 1536] fp32 (only q cols written)
__device__ float g_qinv[B_ * H_ * D_];
__device__ float g_kp[B_ * H_ * P_ * D_];
__device__ float g_vp[B_ * H_ * P_ * D_];
__device__ float g_gram[B_ * C_ * C_];         // half-K partial 0; softmaxed in place
__device__ float g_gram2[B_ * C_ * C_];        // half-K partial 1
__device__ float g_projP[4 * 16 * 64 * 512];   // proj split-K partials
__device__ __nv_bfloat16 g_xh[B_ * N_ * C_],  g_xl[B_ * N_ * C_];    // x [row, 512]
__device__ __nv_bfloat16 g_wqh[3 * C_ * C_],  g_wql[3 * C_ * C_];    // w_qkv [n, 512]
__device__ __nv_bfloat16 g_wo1h[(C_/2) * C_], g_wo1l[(C_/2) * C_];   // w_o1 [n, 512]
__device__ __nv_bfloat16 g_weh[P_ * N_], g_wel[P_ * N_];             // w_e [p, 4096]
__device__ __nv_bfloat16 g_kvh[B_ * N_ * 1024], g_kvl[B_ * N_ * 1024]; // K|V bf16 [row,1024]
__device__ __nv_bfloat16 g_xsah[B_ * N_ * C_], g_xsal[B_ * N_ * C_]; // scrambled x_sa
__device__ __nv_bfloat16 g_Mh[B_ * (C_/2) * C_], g_Ml[B_ * (C_/2) * C_]; // M^T [b,j,k]

typedef __nv_bfloat16 bf16;

__device__ __forceinline__ void split_bf16(float x, bf16& h, bf16& l) {
    h = __float2bfloat16(x);
    l = __float2bfloat16(x - __bfloat162float(h));
}

__device__ __forceinline__ uint32_t smem_u32(const void* p) {
    uint32_t a;
    asm("{ .reg .u64 t; cvta.to.shared.u64 t, %1; cvt.u32.u64 %0, t; }" : "=r"(a) : "l"(p));
    return a;
}
__device__ __forceinline__ void cpasync16(uint32_t dst, const void* src) {
    asm volatile("cp.async.cg.shared.global [%0], [%1], 16;" :: "r"(dst), "l"(src));
}
#define CPCOMMIT() asm volatile("cp.async.commit_group;" ::: "memory")
#define CPWAIT(n)  asm volatile("cp.async.wait_group " #n ";" ::: "memory")

#define RM_STR 24
#define KM128 136

// =====================================================================
// 2-stage padded cp.async wmma core (round-12/13 proven, 1616us config).
// 128x128 CTA tile, 256 threads (8 warps 2m x 4n), K chunks of 16.
// =====================================================================
template <bool ACol, bool BCol>
__device__ __forceinline__ void gemm_wmma4(
    const bf16* __restrict__ Ah, const bf16* __restrict__ Al, int lda,
    const bf16* __restrict__ Bh, const bf16* __restrict__ Bl, int ldb,
    int K, float* __restrict__ Cp, int ldc) {
    using ALay = typename std::conditional<ACol, wmma::col_major, wmma::row_major>::type;
    using BLay = typename std::conditional<BCol, wmma::col_major, wmma::row_major>::type;
    constexpr int ASZ = ACol ? 16 * KM128 : 128 * RM_STR;
    constexpr int BSZ = BCol ? 128 * RM_STR : 16 * KM128;
    __shared__ bf16 sAh[2][ASZ], sAl[2][ASZ];
    __shared__ bf16 sBh[2][BSZ], sBl[2][BSZ];

    int tid = threadIdx.x;
    int wid = tid >> 5;
    int wm = wid & 1, wn = wid >> 1;

    auto PF = [&](int kc, int st) {
        int k0 = kc << 4;
        uint32_t ah = smem_u32(sAh[st]), al = smem_u32(sAl[st]);
        uint32_t bhs = smem_u32(sBh[st]), bls = smem_u32(sBl[st]);
        {
            size_t o; int so;
            if (ACol) { int kr = tid >> 4, q = tid & 15;
                        o = (size_t)(k0 + kr) * lda + q * 8; so = kr * KM128 + q * 8; }
            else      { int row = tid >> 1, q = tid & 1;
                        o = (size_t)row * lda + k0 + q * 8; so = row * RM_STR + q * 8; }
            cpasync16(ah + so * 2, Ah + o);
            cpasync16(al + so * 2, Al + o);
        }
        {
            size_t o; int so;
            if (BCol) { int row = tid >> 1, q = tid & 1;
                        o = (size_t)row * ldb + k0 + q * 8; so = row * RM_STR + q * 8; }
            else      { int kr = tid >> 4, q = tid & 15;
                        o = (size_t)(k0 + kr) * ldb + q * 8; so = kr * KM128 + q * 8; }
            cpasync16(bhs + so * 2, Bh + o);
            cpasync16(bls + so * 2, Bl + o);
        }
        CPCOMMIT();
    };

    wmma::fragment<wmma::accumulator, 16, 16, 16, float> acc[4][2];
#pragma unroll
    for (int i = 0; i < 4; i++)
#pragma unroll
        for (int j = 0; j < 2; j++) wmma::fill_fragment(acc[i][j], 0.0f);

    int nk = K >> 4;
    PF(0, 0);
    for (int kt = 0; kt < nk; kt++) {
        int st = kt & 1;
        if (kt + 1 < nk) { PF(kt + 1, st ^ 1); CPWAIT(1); }
        else             { CPWAIT(0); }
        __syncthreads();
        wmma::fragment<wmma::matrix_a, 16, 16, 16, bf16, ALay> ah[4], al[4];
        wmma::fragment<wmma::matrix_b, 16, 16, 16, bf16, BLay> bh[2], bl[2];
#pragma unroll
        for (int i = 0; i < 4; i++) {
            int m = wm * 64 + i * 16;
            if (ACol) {
                wmma::load_matrix_sync(ah[i], sAh[st] + m, KM128);
                wmma::load_matrix_sync(al[i], sAl[st] + m, KM128);
            } else {
                wmma::load_matrix_sync(ah[i], sAh[st] + m * RM_STR, RM_STR);
                wmma::load_matrix_sync(al[i], sAl[st] + m * RM_STR, RM_STR);
            }
        }
#pragma unroll
        for (int j = 0; j < 2; j++) {
            int n = wn * 32 + j * 16;
            if (BCol) {
                wmma::load_matrix_sync(bh[j], sBh[st] + n * RM_STR, RM_STR);
                wmma::load_matrix_sync(bl[j], sBl[st] + n * RM_STR, RM_STR);
            } else {
                wmma::load_matrix_sync(bh[j], sBh[st] + n, KM128);
                wmma::load_matrix_sync(bl[j], sBl[st] + n, KM128);
            }
        }
#pragma unroll
        for (int i = 0; i < 4; i++)
#pragma unroll
            for (int j = 0; j < 2; j++) {
                wmma::mma_sync(acc[i][j], ah[i], bh[j], acc[i][j]);
                wmma::mma_sync(acc[i][j], ah[i], bl[j], acc[i][j]);
                wmma::mma_sync(acc[i][j], al[i], bh[j], acc[i][j]);
            }
        __syncthreads();
    }
#pragma unroll
    for (int i = 0; i < 4; i++)
#pragma unroll
        for (int j = 0; j < 2; j++) {
            int m = wm * 64 + i * 16, n = wn * 32 + j * 16;
            wmma::store_matrix_sync(Cp + (size_t)m * ldc + n, acc[i][j], ldc,
                                    wmma::mem_row_major);
        }
}

// ================= K1: qkv — q tiles -> fp32 g_qkv; K/V tiles -> bf16 split =====
__global__ __launch_bounds__(256) void k_qkv_w() {
    constexpr int ASZ = 128 * RM_STR, BSZ = 128 * RM_STR;
    __shared__ bf16 sAh[2][ASZ], sAl[2][ASZ];
    __shared__ bf16 sBh[2][BSZ], sBl[2][BSZ];

    int tid = threadIdx.x;
    int wid = tid >> 5, lane = tid & 31;
    int wm = wid & 1, wn = wid >> 1;
    int m0 = blockIdx.y * 128, n0 = blockIdx.x * 128;
    const bf16* Ah = g_xh + (size_t)m0 * 512;
    const bf16* Al = g_xl + (size_t)m0 * 512;
    const bf16* Bh = g_wqh + (size_t)n0 * 512;
    const bf16* Bl = g_wql + (size_t)n0 * 512;

    auto PF = [&](int kc, int st) {
        int k0 = kc << 4;
        uint32_t ah = smem_u32(sAh[st]), al = smem_u32(sAl[st]);
        uint32_t bhs = smem_u32(sBh[st]), bls = smem_u32(sBl[st]);
        int row = tid >> 1, q = tid & 1;
        size_t oa = (size_t)row * 512 + k0 + q * 8;
        int so = row * RM_STR + q * 8;
        cpasync16(ah + so * 2, Ah + oa);
        cpasync16(al + so * 2, Al + oa);
        cpasync16(bhs + so * 2, Bh + oa);
        cpasync16(bls + so * 2, Bl + oa);
        CPCOMMIT();
    };

    wmma::fragment<wmma::accumulator, 16, 16, 16, float> acc[4][2];
#pragma unroll
    for (int i = 0; i < 4; i++)
#pragma unroll
        for (int j = 0; j < 2; j++) wmma::fill_fragment(acc[i][j], 0.0f);

    PF(0, 0);
    for (int kt = 0; kt < 32; kt++) {
        int st = kt & 1;
        if (kt + 1 < 32) { PF(kt + 1, st ^ 1); CPWAIT(1); }
        else             { CPWAIT(0); }
        __syncthreads();
        wmma::fragment<wmma::matrix_a, 16, 16, 16, bf16, wmma::row_major> ah[4], al[4];
        wmma::fragment<wmma::matrix_b, 16, 16, 16, bf16, wmma::col_major> bh[2], bl[2];
#pragma unroll
        for (int i = 0; i < 4; i++) {
            int m = wm * 64 + i * 16;
            wmma::load_matrix_sync(ah[i], sAh[st] + m * RM_STR, RM_STR);
            wmma::load_matrix_sync(al[i], sAl[st] + m * RM_STR, RM_STR);
        }
#pragma unroll
        for (int j = 0; j < 2; j++) {
            int n = wn * 32 + j * 16;
            wmma::load_matrix_sync(bh[j], sBh[st] + n * RM_STR, RM_STR);
            wmma::load_matrix_sync(bl[j], sBl[st] + n * RM_STR, RM_STR);
        }
#pragma unroll
        for (int i = 0; i < 4; i++)
#pragma unroll
            for (int j = 0; j < 2; j++) {
                wmma::mma_sync(acc[i][j], ah[i], bh[j], acc[i][j]);
                wmma::mma_sync(acc[i][j], ah[i], bl[j], acc[i][j]);
                wmma::mma_sync(acc[i][j], al[i], bh[j], acc[i][j]);
            }
        __syncthreads();
    }
    if (n0 < 512) {   // q columns: fp32 to g_qkv
#pragma unroll
        for (int i = 0; i < 4; i++)
#pragma unroll
            for (int j = 0; j < 2; j++) {
                int m = wm * 64 + i * 16, n = wn * 32 + j * 16;
                wmma::store_matrix_sync(g_qkv + (size_t)(m0 + m) * 1536 + n0 + n,
                                        acc[i][j], 1536, wmma::mem_row_major);
            }
    } else {          // K/V columns: bf16 hi/lo split via per-warp smem relay
        __syncthreads();   // all fragment loads done; reuse sBh as scratch
        float* cbuf = reinterpret_cast<float*>(sBh[0]) + wid * 256;
#pragma unroll
        for (int i = 0; i < 4; i++)
#pragma unroll
            for (int j = 0; j < 2; j++) {
                wmma::store_matrix_sync(cbuf, acc[i][j], 16, wmma::mem_row_major);
                __syncwarp();
                int mrow = m0 + wm * 64 + i * 16;
                int col0 = n0 - 512 + wn * 32 + j * 16;
#pragma unroll
                for (int e = lane; e < 256; e += 32) {
                    int r = e >> 4, c = e & 15;
                    bf16 hh, ll;
                    split_bf16(cbuf[e], hh, ll);
                    size_t o = (size_t)(mrow + r) * 1024 + col0 + c;
                    g_kvh[o] = hh;
                    g_kvl[o] = ll;
                }
                __syncwarp();
            }
    }
}

// ================= K4: Gram[b] = X^T X, split-K=2 =================
__global__ __launch_bounds__(256) void k_gram_w() {
    int b = blockIdx.z >> 1, half = blockIdx.z & 1;
    int c10 = blockIdx.y * 128, c20 = blockIdx.x * 128;
    const bf16* xh = g_xh + (size_t)b * N_ * C_ + (size_t)half * 2048 * 512;
    const bf16* xl = g_xl + (size_t)b * N_ * C_ + (size_t)half * 2048 * 512;
    float* dst = (half ? g_gram2 : g_gram) + ((size_t)(b * 512 + c10)) * 512 + c20;
    gemm_wmma4<true, false>(xh + c10, xl + c10, 512, xh + c20, xl + c20, 512,
                            2048, dst, 512);
}

// ================= K8+K9 merged: out halves via blockIdx.z =================
__global__ __launch_bounds__(256) void k_out_w(float* __restrict__ out) {
    int m0 = blockIdx.y * 128, n0 = blockIdx.x * 128;
    if (blockIdx.z == 0) {
        gemm_wmma4<false, true>(g_xsah + (size_t)m0 * 512, g_xsal + (size_t)m0 * 512, 512,
                                g_wo1h + (size_t)n0 * 512, g_wo1l + (size_t)n0 * 512, 512,
                                512, out + (size_t)m0 * 512 + n0, 512);
    } else {
        int b = m0 >> 12;
        gemm_wmma4<false, true>(g_xh + (size_t)m0 * 512, g_xl + (size_t)m0 * 512, 512,
                                g_Mh + ((size_t)b * 256 + n0) * 512,
                                g_Ml + ((size_t)b * 256 + n0) * 512, 512,
                                512, out + (size_t)m0 * 512 + 256 + n0, 512);
    }
}

// ================= K3a: proj partials = w_e @ KV, 64x128 tiles, split-K=4 ======
__global__ __launch_bounds__(128) void k_proj_n() {
    __shared__ bf16 sAh[2][64 * RM_STR], sAl[2][64 * RM_STR];
    __shared__ bf16 sBh[2][16 * KM128], sBl[2][16 * KM128];
    int tid = threadIdx.x;
    int wn = tid >> 5;
    int n0 = blockIdx.x * 128;
    int s = blockIdx.y;          // slab b*2+kv
    int b = s >> 1, kv = s & 1;
    int ks = blockIdx.z;
    const bf16* Ah = g_weh + ks * 1024;
    const bf16* Al = g_wel + ks * 1024;
    const bf16* Bh = g_kvh + (size_t)b * N_ * 1024 + (size_t)ks * 1024 * 1024 + kv * 512 + n0;
    const bf16* Bl = g_kvl + (size_t)b * N_ * 1024 + (size_t)ks * 1024 * 1024 + kv * 512 + n0;

    auto PF = [&](int kc, int st) {
        int k0 = kc << 4;
        uint32_t ah = smem_u32(sAh[st]), al = smem_u32(sAl[st]);
        uint32_t bhs = smem_u32(sBh[st]), bls = smem_u32(sBl[st]);
        {
            int row = tid >> 1, q = tid & 1;
            size_t o = (size_t)row * N_ + k0 + q * 8;
            int so = row * RM_STR + q * 8;
            cpasync16(ah + so * 2, Ah + o);
            cpasync16(al + so * 2, Al + o);
        }
#pragma unroll
        for (int u = 0; u < 2; u++) {
            int idx = u * 128 + tid;
            int kr = idx >> 4, q = idx & 15;
            size_t o = (size_t)(k0 + kr) * 1024 + q * 8;
            int so = kr * KM128 + q * 8;
            cpasync16(bhs + so * 2, Bh + o);
            cpasync16(bls + so * 2, Bl + o);
        }
        CPCOMMIT();
    };

    wmma::fragment<wmma::accumulator, 16, 16, 16, float> acc[4][2];
#pragma unroll
    for (int i = 0; i < 4; i++)
#pragma unroll
        for (int j = 0; j < 2; j++) wmma::fill_fragment(acc[i][j], 0.0f);

    PF(0, 0);
    for (int kt = 0; kt < 64; kt++) {    // K=1024
        int st = kt & 1;
        if (kt + 1 < 64) { PF(kt + 1, st ^ 1); CPWAIT(1); }
        else             { CPWAIT(0); }
        __syncthreads();
        wmma::fragment<wmma::matrix_a, 16, 16, 16, bf16, wmma::row_major> ah[4], al[4];
        wmma::fragment<wmma::matrix_b, 16, 16, 16, bf16, wmma::row_major> bh[2], bl[2];
#pragma unroll
        for (int i = 0; i < 4; i++) {
            wmma::load_matrix_sync(ah[i], sAh[st] + i * 16 * RM_STR, RM_STR);
            wmma::load_matrix_sync(al[i], sAl[st] + i * 16 * RM_STR, RM_STR);
        }
#pragma unroll
        for (int j = 0; j < 2; j++) {
            int n = wn * 32 + j * 16;
            wmma::load_matrix_sync(bh[j], sBh[st] + n, KM128);
            wmma::load_matrix_sync(bl[j], sBl[st] + n, KM128);
        }
#pragma unroll
        for (int i = 0; i < 4; i++)
#pragma unroll
            for (int j = 0; j < 2; j++) {
                wmma::mma_sync(acc[i][j], ah[i], bh[j], acc[i][j]);
                wmma::mma_sync(acc[i][j], ah[i], bl[j], acc[i][j]);
                wmma::mma_sync(acc[i][j], al[i], bh[j], acc[i][j]);
            }
        __syncthreads();
    }
    float* Cp = g_projP + (((size_t)ks * 16 + s) * 64) * 512 + n0;
#pragma unroll
    for (int i = 0; i < 4; i++)
#pragma unroll
        for (int j = 0; j < 2; j++)
            wmma::store_matrix_sync(Cp + (size_t)(i * 16) * 512 + wn * 32 + j * 16,
                                    acc[i][j], 512, wmma::mem_row_major);
}

// ================= K3b: reduce proj partials + b_e -> g_kp/g_vp ================
__global__ __launch_bounds__(256) void k_proj_red(const float* __restrict__ b_e) {
    int s = blockIdx.y;
    int e0 = (blockIdx.x * 256 + threadIdx.x) * 4;
    int p = e0 >> 9, d = e0 & 511;
    float4 acc = make_float4(0.f, 0.f, 0.f, 0.f);
#pragma unroll
    for (int ks = 0; ks < 4; ks++) {
        float4 v = *(const float4*)(g_projP + (((size_t)ks * 16 + s) * 64 + p) * 512 + d);
        acc.x += v.x; acc.y += v.y; acc.z += v.z; acc.w += v.w;
    }
    float be = b_e[p];
    acc.x += be; acc.y += be; acc.z += be; acc.w += be;
    int b = s >> 1, kv = s & 1, h = d >> 6, dd = d & 63;
    float* dst = (kv ? g_vp : g_kp) + (((size_t)(b * 8 + h) * 64 + p) * 64 + dd);
    *(float4*)dst = acc;
}

// ================= bias epilogue: out[r][c] += b_o1/b_o2 =================
__global__ __launch_bounds__(256) void k_bias(const float* __restrict__ b_o1,
                                              const float* __restrict__ b_o2,
                                              float* __restrict__ out) {
    size_t i = ((size_t)blockIdx.x * 256 + threadIdx.x) * 4;
    int c = (int)(i & 511);
    const float* bias = (c < 256) ? (b_o1 + c) : (b_o2 + c - 256);
    float4 v = *(float4*)(out + i);
    float4 bb = *(const float4*)bias;
    v.x += bb.x; v.y += bb.y; v.z += bb.z; v.w += bb.w;
    *(float4*)(out + i) = v;
}

// ================= conversions (destinations referenced in DEVICE code) =====
__device__ __forceinline__ void split4_to(const float* __restrict__ s,
                                          bf16* __restrict__ h,
                                          bf16* __restrict__ l, size_t i) {
    float4 v = *(const float4*)(s + i);
    bf16 hh[4], ll[4];
    split_bf16(v.x, hh[0], ll[0]); split_bf16(v.y, hh[1], ll[1]);
    split_bf16(v.z, hh[2], ll[2]); split_bf16(v.w, hh[3], ll[3]);
    *(uint2*)(h + i) = *(uint2*)hh;
    *(uint2*)(l + i) = *(uint2*)ll;
}

__global__ void c_split_x(const float* __restrict__ s) {
    size_t i = ((size_t)blockIdx.x * 256 + threadIdx.x) * 4;
    split4_to(s, g_xh, g_xl, i);
}
// merged weight conversions: wq (768 blocks) | wo1 (128) | we (256)
__global__ void c_split_w(const float* __restrict__ wq,
                          const float* __restrict__ wo1,
                          const float* __restrict__ we) {
    int blk = blockIdx.x;
    if (blk < 768) {
        size_t i = ((size_t)blk * 256 + threadIdx.x) * 4;
        split4_to(wq, g_wqh, g_wql, i);
    } else if (blk < 896) {
        size_t i = ((size_t)(blk - 768) * 256 + threadIdx.x) * 4;
        split4_to(wo1, g_wo1h, g_wo1l, i);
    } else {
        size_t i = ((size_t)(blk - 896) * 256 + threadIdx.x) * 4;
        split4_to(we, g_weh, g_wel, i);
    }
}

// ================= K2: q token-axis L2 norm inverses (coalesced) =============
__global__ __launch_bounds__(256) void k_qnorm() {
    int bh = blockIdx.x;
    int b = bh >> 3, h = bh & 7;
    int tid = threadIdx.x;
    int rg = tid >> 4;
    int q4 = tid & 15;
    const float* base = g_qkv + (size_t)b * (N_ * 1536) + h * 64 + q4 * 4;
    float4 s = make_float4(0.f, 0.f, 0.f, 0.f);
    for (int n = rg; n < N_; n += 16) {
        float4 v = *(const float4*)(base + (size_t)n * 1536);
        s.x += v.x * v.x; s.y += v.y * v.y; s.z += v.z * v.z; s.w += v.w * v.w;
    }
    __shared__ float4 red[16][16];
    red[rg][q4] = s;
    __syncthreads();
    if (tid < 16) {
        float4 tot = red[0][tid];
#pragma unroll
        for (int r = 1; r < 16; r++) {
            float4 v = red[r][tid];
            tot.x += v.x; tot.y += v.y; tot.z += v.z; tot.w += v.w;
        }
        float* dst = g_qinv + bh * 64 + tid * 4;
        dst[0] = 1.f / fmaxf(sqrtf(tot.x), 1e-12f);
        dst[1] = 1.f / fmaxf(sqrtf(tot.y), 1e-12f);
        dst[2] = 1.f / fmaxf(sqrtf(tot.z), 1e-12f);
        dst[3] = 1.f / fmaxf(sqrtf(tot.w), 1e-12f);
    }
}

// ================= K5: row softmax of (gram+gram2) * temperature =============
__global__ __launch_bounds__(256) void k_softmax512(const float* __restrict__ temp) {
    int row = blockIdx.x;
    float t = temp[0];
    float* p = g_gram + (size_t)row * 512;
    const float* p2 = g_gram2 + (size_t)row * 512;
    int tid = threadIdx.x;
    __shared__ float red[256];
    float v0 = (p[tid] + p2[tid]) * t;
    float v1 = (p[tid + 256] + p2[tid + 256]) * t;
    red[tid] = fmaxf(v0, v1);
    __syncthreads();
    for (int s = 128; s > 0; s >>= 1) {
        if (tid < s) red[tid] = fmaxf(red[tid], red[tid + s]);
        __syncthreads();
    }
    float mx = red[0];
    __syncthreads();
    float e0 = __expf(v0 - mx), e1 = __expf(v1 - mx);
    red[tid] = e0 + e1;
    __syncthreads();
    for (int s = 128; s > 0; s >>= 1) {
        if (tid < s) red[tid] += red[tid + s];
        __syncthreads();
    }
    float inv = 1.f / red[0];
    p[tid] = e0 * inv;
    p[tid + 256] = e1 * inv;
}

// ================= K6: fused spatial attention (writes bf16 hi/lo) =================
__global__ __launch_bounds__(128) void k_sa(const float* __restrict__ temp2) {
    __shared__ float kp_s[P_ * D_];
    __shared__ float vp_s[P_ * D_];
    __shared__ float qi_s[D_];
    int bh = blockIdx.y;
    int b = bh >> 3, h = bh & 7;
    int n = blockIdx.x * 128 + threadIdx.x;
    const float4* kp4 = (const float4*)(g_kp + bh * (P_ * D_));
    const float4* vp4 = (const float4*)(g_vp + bh * (P_ * D_));
    for (int i = threadIdx.x; i < (P_ * D_) / 4; i += 128) {
        ((float4*)kp_s)[i] = kp4[i];
        ((float4*)vp_s)[i] = vp4[i];
    }
    if (threadIdx.x < 64) qi_s[threadIdx.x] = g_qinv[bh * 64 + threadIdx.x];
    __syncthreads();
    float t2 = temp2[h];
    const float* qrow = g_qkv + (size_t)b * (N_ * 1536) + (size_t)n * 1536 + h * 64;

    float q[64];
#pragma unroll
    for (int d = 0; d < 64; d++) q[d] = qrow[d] * qi_s[d];

    float s[64];
    float mx = -1e30f;
#pragma unroll
    for (int p = 0; p < 64; p++) {
        float acc = 0.f;
#pragma unroll
        for (int d = 0; d < 64; d += 4) {
            float4 k4 = *(const float4*)&kp_s[p * 64 + d];
            acc += q[d] * k4.x + q[d + 1] * k4.y + q[d + 2] * k4.z + q[d + 3] * k4.w;
        }
        s[p] = acc * t2;
        mx = fmaxf(mx, s[p]);
    }
    float sum = 0.f;
#pragma unroll
    for (int p = 0; p < 64; p++) {
        s[p] = __expf(s[p] - mx);
        sum += s[p];
    }
    float inv = 1.f / sum;

    float o[64];
#pragma unroll
    for (int d = 0; d < 64; d++) o[d] = 0.f;
#pragma unroll
    for (int p = 0; p < 64; p++) {
        float sp = s[p] * inv;
#pragma unroll
        for (int d = 0; d < 64; d += 4) {
            float4 v4 = *(const float4*)&vp_s[p * 64 + d];
            o[d] += sp * v4.x;
            o[d + 1] += sp * v4.y;
            o[d + 2] += sp * v4.z;
            o[d + 3] += sp * v4.w;
        }
    }
    int rbase = h * 8 + (n >> 9);
    int col = n & 511;
    size_t boff = (size_t)b * (N_ * C_);
#pragma unroll
    for (int d = 0; d < 64; d++) {
        bf16 hh, ll;
        split_bf16(o[d], hh, ll);
        size_t idx = boff + (size_t)(d * 64 + rbase) * 512 + col;
        g_xsah[idx] = hh;
        g_xsal[idx] = ll;
    }
}

// ================= K7: M^T[b,j,k] = (attn^T @ w_o2^T)^T, bf16 hi/lo out =================
#define SP2 132
__device__ __forceinline__ void gemmM(
    const float* __restrict__ A, int lda, const float* __restrict__ B, int ldb,
    int K, float (&acc)[8][8], float (*As)[8][SP2], float (*Bs)[8][SP2]) {
    int tid = threadIdx.x;
    int tx = tid & 15, ty = tid >> 4;
    int rowT = tid >> 1, kqT = (tid & 1) * 4;
    int krD = tid >> 5, mqD = (tid & 31) * 4;
    float4 ra, rb;
    auto loadA = [&](int k0) { ra = *(const float4*)&A[(size_t)(k0 + krD) * lda + mqD]; };
    auto loadB = [&](int k0) { rb = *(const float4*)&B[(size_t)rowT * ldb + k0 + kqT]; };
    auto storeA = [&](int buf) { *(float4*)&As[buf][krD][mqD] = ra; };
    auto storeB = [&](int buf) {
        Bs[buf][kqT + 0][rowT] = rb.x; Bs[buf][kqT + 1][rowT] = rb.y;
        Bs[buf][kqT + 2][rowT] = rb.z; Bs[buf][kqT + 3][rowT] = rb.w;
    };
    loadA(0); loadB(0); storeA(0); storeB(0);
    __syncthreads();
    int nk = K >> 3;
    for (int kt = 0; kt < nk; kt++) {
        int cur = kt & 1;
        if (kt + 1 < nk) { loadA((kt + 1) << 3); loadB((kt + 1) << 3); }
#pragma unroll
        for (int kk = 0; kk < 8; kk++) {
            float4 a0 = *(const float4*)&As[cur][kk][ty * 8];
            float4 a1 = *(const float4*)&As[cur][kk][ty * 8 + 4];
            float4 b0 = *(const float4*)&Bs[cur][kk][tx * 8];
            float4 b1 = *(const float4*)&Bs[cur][kk][tx * 8 + 4];
            float a[8] = {a0.x, a0.y, a0.z, a0.w, a1.x, a1.y, a1.z, a1.w};
            float b[8] = {b0.x, b0.y, b0.z, b0.w, b1.x, b1.y, b1.z, b1.w};
#pragma unroll
            for (int i = 0; i < 8; i++)
#pragma unroll
                for (int j = 0; j < 8; j++) acc[i][j] += a[i] * b[j];
        }
        if (kt + 1 < nk) { storeA(cur ^ 1); storeB(cur ^ 1); __syncthreads(); }
    }
}

__global__ __launch_bounds__(256) void k_M(const float* __restrict__ w_o2) {
    __shared__ float As[2][8][SP2];
    __shared__ float Bs[2][8][SP2];
    int b = blockIdx.z;
    int m0 = blockIdx.y * 128;
    int n0 = blockIdx.x * 128;
    const float* A = g_gram + (size_t)b * (512 * 512);
    float acc[8][8] = {};
    gemmM(A + m0, 512, w_o2 + (size_t)n0 * 512, 512, 512, acc, As, Bs);
    int tx = threadIdx.x & 15, ty = threadIdx.x >> 4;
#pragma unroll
    for (int i = 0; i < 8; i++) {
        int k = m0 + ty * 8 + i;
#pragma unroll
        for (int jj = 0; jj < 8; jj++) {
            int j = n0 + tx * 8 + jj;
            bf16 hh, ll;
            split_bf16(acc[i][jj], hh, ll);
            size_t idx = ((size_t)b * 256 + j) * 512 + k;
            g_Mh[idx] = hh;
            g_Ml[idx] = ll;
        }
    }
}

// ================= launch =================
extern "C" void kernel_launch(void* const* d_in, const int* in_sizes, int n_in,
                              void* d_out, int out_size) {
    const float* x      = (const float*)d_in[0];
    const float* w_qkv  = (const float*)d_in[1];
    const float* w_e    = (const float*)d_in[2];
    const float* b_e    = (const float*)d_in[3];
    const float* temp   = (const float*)d_in[4];
    const float* temp2  = (const float*)d_in[5];
    const float* w_o1   = (const float*)d_in[6];
    const float* b_o1   = (const float*)d_in[7];
    const float* w_o2   = (const float*)d_in[8];
    const float* b_o2   = (const float*)d_in[9];
    float* out = (float*)d_out;

    // bf16 hi/lo conversions (globals referenced inside kernels only)
    c_split_x<<<(B_ * N_ * C_) / 1024, 256>>>(x);
    c_split_w<<<768 + 128 + 256, 256>>>(w_qkv, w_o1, w_e);

    k_qkv_w<<<dim3(12, 256), 256>>>();            // q->fp32, K/V->bf16 split
    k_qnorm<<<64, 256>>>();
    k_proj_n<<<dim3(4, 16, 4), 128>>>();          // split-K=4 partials
    k_proj_red<<<dim3(32, 16), 256>>>(b_e);
    k_gram_w<<<dim3(4, 4, 16), 256>>>();          // split-K=2
    k_softmax512<<<B_ * C_, 256>>>(temp);
    k_sa<<<dim3(32, 64), 128>>>(temp2);
    k_M<<<dim3(2, 4, 8), 256>>>(w_o2);
    k_out_w<<<dim3(2, 256, 2), 256>>>(out);       // merged out1+out2
    k_bias<<<(B_ * N_ * C_) / 1024, 256>>>(b_o1, b_o2, out);
}

// round 16
// speedup vs baseline: 1.0568x; 1.0134x over previous
#include <cuda_runtime.h>
#include <cuda_bf16.h>
#include <mma.h>
#include <type_traits>
#include <math.h>
#include <cstdint>

using namespace nvcuda;

// Problem constants
#define B_ 8
#define N_ 4096
#define C_ 512
#define H_ 8
#define P_ 64
#define D_ 64

// ---------------- scratch (device globals; no runtime allocation) ----------------
// NOTE: device globals must ONLY be referenced from device code (GB300 ATS
// makes host-shadow writes silently succeed into host memory otherwise).
__device__ float g_qkv[B_ * N_ * 3 * C_];      // [b, n, 1536] fp32 (only q cols written)
__device__ float g_qinv[B_ * H_ * D_];
__device__ float g_qsum[B_ * H_ * 8 * D_];     // qnorm partials [bh][slice][d]
__device__ float g_kp[B_ * H_ * P_ * D_];
__device__ float g_vp[B_ * H_ * P_ * D_];
__device__ float g_gram[B_ * C_ * C_];         // half-K partial 0; softmaxed in place
__device__ float g_gram2[B_ * C_ * C_];        // half-K partial 1
__device__ float g_projP[4 * 16 * 64 * 512];   // proj split-K partials
__device__ __nv_bfloat16 g_xh[B_ * N_ * C_],  g_xl[B_ * N_ * C_];    // x [row, 512]
__device__ __nv_bfloat16 g_wqh[3 * C_ * C_],  g_wql[3 * C_ * C_];    // w_qkv [n, 512]
__device__ __nv_bfloat16 g_wo1h[(C_/2) * C_], g_wo1l[(C_/2) * C_];   // w_o1 [n, 512]
__device__ __nv_bfloat16 g_weh[P_ * N_], g_wel[P_ * N_];             // w_e [p, 4096]
__device__ __nv_bfloat16 g_kvh[B_ * N_ * 1024], g_kvl[B_ * N_ * 1024]; // K|V bf16 [row,1024]
__device__ __nv_bfloat16 g_xsah[B_ * N_ * C_], g_xsal[B_ * N_ * C_]; // scrambled x_sa
__device__ __nv_bfloat16 g_Mh[B_ * (C_/2) * C_], g_Ml[B_ * (C_/2) * C_]; // M^T [b,j,k]

typedef __nv_bfloat16 bf16;

__device__ __forceinline__ void split_bf16(float x, bf16& h, bf16& l) {
    h = __float2bfloat16(x);
    l = __float2bfloat16(x - __bfloat162float(h));
}

__device__ __forceinline__ uint32_t smem_u32(const void* p) {
    uint32_t a;
    asm("{ .reg .u64 t; cvta.to.shared.u64 t, %1; cvt.u32.u64 %0, t; }" : "=r"(a) : "l"(p));
    return a;
}
__device__ __forceinline__ void cpasync16(uint32_t dst, const void* src) {
    asm volatile("cp.async.cg.shared.global [%0], [%1], 16;" :: "r"(dst), "l"(src));
}
#define CPCOMMIT() asm volatile("cp.async.commit_group;" ::: "memory")
#define CPWAIT(n)  asm volatile("cp.async.wait_group " #n ";" ::: "memory")

#define RM_STR 24
#define KM128 136

// =====================================================================
// 2-stage padded cp.async wmma core (round-12/13 proven, 1616us config).
// 128x128 CTA tile, 256 threads (8 warps 2m x 4n), K chunks of 16.
// =====================================================================
template <bool ACol, bool BCol>
__device__ __forceinline__ void gemm_wmma4(
    const bf16* __restrict__ Ah, const bf16* __restrict__ Al, int lda,
    const bf16* __restrict__ Bh, const bf16* __restrict__ Bl, int ldb,
    int K, float* __restrict__ Cp, int ldc) {
    using ALay = typename std::conditional<ACol, wmma::col_major, wmma::row_major>::type;
    using BLay = typename std::conditional<BCol, wmma::col_major, wmma::row_major>::type;
    constexpr int ASZ = ACol ? 16 * KM128 : 128 * RM_STR;
    constexpr int BSZ = BCol ? 128 * RM_STR : 16 * KM128;
    __shared__ bf16 sAh[2][ASZ], sAl[2][ASZ];
    __shared__ bf16 sBh[2][BSZ], sBl[2][BSZ];

    int tid = threadIdx.x;
    int wid = tid >> 5;
    int wm = wid & 1, wn = wid >> 1;

    auto PF = [&](int kc, int st) {
        int k0 = kc << 4;
        uint32_t ah = smem_u32(sAh[st]), al = smem_u32(sAl[st]);
        uint32_t bhs = smem_u32(sBh[st]), bls = smem_u32(sBl[st]);
        {
            size_t o; int so;
            if (ACol) { int kr = tid >> 4, q = tid & 15;
                        o = (size_t)(k0 + kr) * lda + q * 8; so = kr * KM128 + q * 8; }
            else      { int row = tid >> 1, q = tid & 1;
                        o = (size_t)row * lda + k0 + q * 8; so = row * RM_STR + q * 8; }
            cpasync16(ah + so * 2, Ah + o);
            cpasync16(al + so * 2, Al + o);
        }
        {
            size_t o; int so;
            if (BCol) { int row = tid >> 1, q = tid & 1;
                        o = (size_t)row * ldb + k0 + q * 8; so = row * RM_STR + q * 8; }
            else      { int kr = tid >> 4, q = tid & 15;
                        o = (size_t)(k0 + kr) * ldb + q * 8; so = kr * KM128 + q * 8; }
            cpasync16(bhs + so * 2, Bh + o);
            cpasync16(bls + so * 2, Bl + o);
        }
        CPCOMMIT();
    };

    wmma::fragment<wmma::accumulator, 16, 16, 16, float> acc[4][2];
#pragma unroll
    for (int i = 0; i < 4; i++)
#pragma unroll
        for (int j = 0; j < 2; j++) wmma::fill_fragment(acc[i][j], 0.0f);

    int nk = K >> 4;
    PF(0, 0);
    for (int kt = 0; kt < nk; kt++) {
        int st = kt & 1;
        if (kt + 1 < nk) { PF(kt + 1, st ^ 1); CPWAIT(1); }
        else             { CPWAIT(0); }
        __syncthreads();
        wmma::fragment<wmma::matrix_a, 16, 16, 16, bf16, ALay> ah[4], al[4];
        wmma::fragment<wmma::matrix_b, 16, 16, 16, bf16, BLay> bh[2], bl[2];
#pragma unroll
        for (int i = 0; i < 4; i++) {
            int m = wm * 64 + i * 16;
            if (ACol) {
                wmma::load_matrix_sync(ah[i], sAh[st] + m, KM128);
                wmma::load_matrix_sync(al[i], sAl[st] + m, KM128);
            } else {
                wmma::load_matrix_sync(ah[i], sAh[st] + m * RM_STR, RM_STR);
                wmma::load_matrix_sync(al[i], sAl[st] + m * RM_STR, RM_STR);
            }
        }
#pragma unroll
        for (int j = 0; j < 2; j++) {
            int n = wn * 32 + j * 16;
            if (BCol) {
                wmma::load_matrix_sync(bh[j], sBh[st] + n * RM_STR, RM_STR);
                wmma::load_matrix_sync(bl[j], sBl[st] + n * RM_STR, RM_STR);
            } else {
                wmma::load_matrix_sync(bh[j], sBh[st] + n, KM128);
                wmma::load_matrix_sync(bl[j], sBl[st] + n, KM128);
            }
        }
#pragma unroll
        for (int i = 0; i < 4; i++)
#pragma unroll
            for (int j = 0; j < 2; j++) {
                wmma::mma_sync(acc[i][j], ah[i], bh[j], acc[i][j]);
                wmma::mma_sync(acc[i][j], ah[i], bl[j], acc[i][j]);
                wmma::mma_sync(acc[i][j], al[i], bh[j], acc[i][j]);
            }
        __syncthreads();
    }
#pragma unroll
    for (int i = 0; i < 4; i++)
#pragma unroll
        for (int j = 0; j < 2; j++) {
            int m = wm * 64 + i * 16, n = wn * 32 + j * 16;
            wmma::store_matrix_sync(Cp + (size_t)m * ldc + n, acc[i][j], ldc,
                                    wmma::mem_row_major);
        }
}

// ================= K1: qkv — q tiles -> fp32 g_qkv; K/V tiles -> bf16 split =====
__global__ __launch_bounds__(256) void k_qkv_w() {
    constexpr int ASZ = 128 * RM_STR, BSZ = 128 * RM_STR;
    __shared__ bf16 sAh[2][ASZ], sAl[2][ASZ];
    __shared__ bf16 sBh[2][BSZ], sBl[2][BSZ];

    int tid = threadIdx.x;
    int wid = tid >> 5, lane = tid & 31;
    int wm = wid & 1, wn = wid >> 1;
    int m0 = blockIdx.y * 128, n0 = blockIdx.x * 128;
    const bf16* Ah = g_xh + (size_t)m0 * 512;
    const bf16* Al = g_xl + (size_t)m0 * 512;
    const bf16* Bh = g_wqh + (size_t)n0 * 512;
    const bf16* Bl = g_wql + (size_t)n0 * 512;

    auto PF = [&](int kc, int st) {
        int k0 = kc << 4;
        uint32_t ah = smem_u32(sAh[st]), al = smem_u32(sAl[st]);
        uint32_t bhs = smem_u32(sBh[st]), bls = smem_u32(sBl[st]);
        int row = tid >> 1, q = tid & 1;
        size_t oa = (size_t)row * 512 + k0 + q * 8;
        int so = row * RM_STR + q * 8;
        cpasync16(ah + so * 2, Ah + oa);
        cpasync16(al + so * 2, Al + oa);
        cpasync16(bhs + so * 2, Bh + oa);
        cpasync16(bls + so * 2, Bl + oa);
        CPCOMMIT();
    };

    wmma::fragment<wmma::accumulator, 16, 16, 16, float> acc[4][2];
#pragma unroll
    for (int i = 0; i < 4; i++)
#pragma unroll
        for (int j = 0; j < 2; j++) wmma::fill_fragment(acc[i][j], 0.0f);

    PF(0, 0);
    for (int kt = 0; kt < 32; kt++) {
        int st = kt & 1;
        if (kt + 1 < 32) { PF(kt + 1, st ^ 1); CPWAIT(1); }
        else             { CPWAIT(0); }
        __syncthreads();
        wmma::fragment<wmma::matrix_a, 16, 16, 16, bf16, wmma::row_major> ah[4], al[4];
        wmma::fragment<wmma::matrix_b, 16, 16, 16, bf16, wmma::col_major> bh[2], bl[2];
#pragma unroll
        for (int i = 0; i < 4; i++) {
            int m = wm * 64 + i * 16;
            wmma::load_matrix_sync(ah[i], sAh[st] + m * RM_STR, RM_STR);
            wmma::load_matrix_sync(al[i], sAl[st] + m * RM_STR, RM_STR);
        }
#pragma unroll
        for (int j = 0; j < 2; j++) {
            int n = wn * 32 + j * 16;
            wmma::load_matrix_sync(bh[j], sBh[st] + n * RM_STR, RM_STR);
            wmma::load_matrix_sync(bl[j], sBl[st] + n * RM_STR, RM_STR);
        }
#pragma unroll
        for (int i = 0; i < 4; i++)
#pragma unroll
            for (int j = 0; j < 2; j++) {
                wmma::mma_sync(acc[i][j], ah[i], bh[j], acc[i][j]);
                wmma::mma_sync(acc[i][j], ah[i], bl[j], acc[i][j]);
                wmma::mma_sync(acc[i][j], al[i], bh[j], acc[i][j]);
            }
        __syncthreads();
    }
    if (n0 < 512) {   // q columns: fp32 to g_qkv
#pragma unroll
        for (int i = 0; i < 4; i++)
#pragma unroll
            for (int j = 0; j < 2; j++) {
                int m = wm * 64 + i * 16, n = wn * 32 + j * 16;
                wmma::store_matrix_sync(g_qkv + (size_t)(m0 + m) * 1536 + n0 + n,
                                        acc[i][j], 1536, wmma::mem_row_major);
            }
    } else {          // K/V columns: bf16 hi/lo split via per-warp smem relay
        __syncthreads();   // all fragment loads done; reuse sBh as scratch
        float* cbuf = reinterpret_cast<float*>(sBh[0]) + wid * 256;
#pragma unroll
        for (int i = 0; i < 4; i++)
#pragma unroll
            for (int j = 0; j < 2; j++) {
                wmma::store_matrix_sync(cbuf, acc[i][j], 16, wmma::mem_row_major);
                __syncwarp();
                int mrow = m0 + wm * 64 + i * 16;
                int col0 = n0 - 512 + wn * 32 + j * 16;
#pragma unroll
                for (int e = lane; e < 256; e += 32) {
                    int r = e >> 4, c = e & 15;
                    bf16 hh, ll;
                    split_bf16(cbuf[e], hh, ll);
                    size_t o = (size_t)(mrow + r) * 1024 + col0 + c;
                    g_kvh[o] = hh;
                    g_kvl[o] = ll;
                }
                __syncwarp();
            }
    }
}

// ================= K4: Gram[b] = X^T X, split-K=2 =================
__global__ __launch_bounds__(256) void k_gram_w() {
    int b = blockIdx.z >> 1, half = blockIdx.z & 1;
    int c10 = blockIdx.y * 128, c20 = blockIdx.x * 128;
    const bf16* xh = g_xh + (size_t)b * N_ * C_ + (size_t)half * 2048 * 512;
    const bf16* xl = g_xl + (size_t)b * N_ * C_ + (size_t)half * 2048 * 512;
    float* dst = (half ? g_gram2 : g_gram) + ((size_t)(b * 512 + c10)) * 512 + c20;
    gemm_wmma4<true, false>(xh + c10, xl + c10, 512, xh + c20, xl + c20, 512,
                            2048, dst, 512);
}

// ================= K8+K9 merged with fused bias epilogue =================
__global__ __launch_bounds__(256) void k_out_w(const float* __restrict__ b_o1,
                                               const float* __restrict__ b_o2,
                                               float* __restrict__ out) {
    constexpr int ASZ = 128 * RM_STR, BSZ = 128 * RM_STR;
    __shared__ bf16 sAh[2][ASZ], sAl[2][ASZ];
    __shared__ bf16 sBh[2][BSZ], sBl[2][BSZ];

    int tid = threadIdx.x;
    int wid = tid >> 5, lane = tid & 31;
    int wm = wid & 1, wn = wid >> 1;
    int m0 = blockIdx.y * 128, n0 = blockIdx.x * 128;
    const bf16 *Ah, *Al, *Bh, *Bl;
    const float* bias;
    int cofs;
    if (blockIdx.z == 0) {
        Ah = g_xsah + (size_t)m0 * 512; Al = g_xsal + (size_t)m0 * 512;
        Bh = g_wo1h + (size_t)n0 * 512; Bl = g_wo1l + (size_t)n0 * 512;
        bias = b_o1; cofs = 0;
    } else {
        int b = m0 >> 12;
        Ah = g_xh + (size_t)m0 * 512; Al = g_xl + (size_t)m0 * 512;
        Bh = g_Mh + ((size_t)b * 256 + n0) * 512;
        Bl = g_Ml + ((size_t)b * 256 + n0) * 512;
        bias = b_o2; cofs = 256;
    }

    auto PF = [&](int kc, int st) {
        int k0 = kc << 4;
        uint32_t ah = smem_u32(sAh[st]), al = smem_u32(sAl[st]);
        uint32_t bhs = smem_u32(sBh[st]), bls = smem_u32(sBl[st]);
        int row = tid >> 1, q = tid & 1;
        size_t o = (size_t)row * 512 + k0 + q * 8;
        int so = row * RM_STR + q * 8;
        cpasync16(ah + so * 2, Ah + o);
        cpasync16(al + so * 2, Al + o);
        cpasync16(bhs + so * 2, Bh + o);
        cpasync16(bls + so * 2, Bl + o);
        CPCOMMIT();
    };

    wmma::fragment<wmma::accumulator, 16, 16, 16, float> acc[4][2];
#pragma unroll
    for (int i = 0; i < 4; i++)
#pragma unroll
        for (int j = 0; j < 2; j++) wmma::fill_fragment(acc[i][j], 0.0f);

    PF(0, 0);
    for (int kt = 0; kt < 32; kt++) {
        int st = kt & 1;
        if (kt + 1 < 32) { PF(kt + 1, st ^ 1); CPWAIT(1); }
        else             { CPWAIT(0); }
        __syncthreads();
        wmma::fragment<wmma::matrix_a, 16, 16, 16, bf16, wmma::row_major> ah[4], al[4];
        wmma::fragment<wmma::matrix_b, 16, 16, 16, bf16, wmma::col_major> bh[2], bl[2];
#pragma unroll
        for (int i = 0; i < 4; i++) {
            int m = wm * 64 + i * 16;
            wmma::load_matrix_sync(ah[i], sAh[st] + m * RM_STR, RM_STR);
            wmma::load_matrix_sync(al[i], sAl[st] + m * RM_STR, RM_STR);
        }
#pragma unroll
        for (int j = 0; j < 2; j++) {
            int n = wn * 32 + j * 16;
            wmma::load_matrix_sync(bh[j], sBh[st] + n * RM_STR, RM_STR);
            wmma::load_matrix_sync(bl[j], sBl[st] + n * RM_STR, RM_STR);
        }
#pragma unroll
        for (int i = 0; i < 4; i++)
#pragma unroll
            for (int j = 0; j < 2; j++) {
                wmma::mma_sync(acc[i][j], ah[i], bh[j], acc[i][j]);
                wmma::mma_sync(acc[i][j], ah[i], bl[j], acc[i][j]);
                wmma::mma_sync(acc[i][j], al[i], bh[j], acc[i][j]);
            }
        __syncthreads();
    }
    // bias epilogue via per-warp smem relay
    __syncthreads();
    float* cbuf = reinterpret_cast<float*>(sAh[0]) + wid * 256;   // 8KB of 12KB region
#pragma unroll
    for (int i = 0; i < 4; i++)
#pragma unroll
        for (int j = 0; j < 2; j++) {
            wmma::store_matrix_sync(cbuf, acc[i][j], 16, wmma::mem_row_major);
            __syncwarp();
            int mrow = m0 + wm * 64 + i * 16;
            int coln = n0 + wn * 32 + j * 16;   // bias index base
            int r = lane >> 1, c = (lane & 1) * 8;
            float* dst = out + (size_t)(mrow + r) * 512 + cofs + coln + c;
            const float* bp = bias + coln + c;
            float4 v0 = *(float4*)&cbuf[r * 16 + c];
            float4 b0 = *(const float4*)bp;
            v0.x += b0.x; v0.y += b0.y; v0.z += b0.z; v0.w += b0.w;
            *(float4*)dst = v0;
            float4 v1 = *(float4*)&cbuf[r * 16 + c + 4];
            float4 b1 = *(const float4*)(bp + 4);
            v1.x += b1.x; v1.y += b1.y; v1.z += b1.z; v1.w += b1.w;
            *(float4*)(dst + 4) = v1;
            __syncwarp();
        }
}

// ================= K3a: proj partials = w_e @ KV, 64x128 tiles, split-K=4 ======
__global__ __launch_bounds__(128) void k_proj_n() {
    __shared__ bf16 sAh[2][64 * RM_STR], sAl[2][64 * RM_STR];
    __shared__ bf16 sBh[2][16 * KM128], sBl[2][16 * KM128];
    int tid = threadIdx.x;
    int wn = tid >> 5;
    int n0 = blockIdx.x * 128;
    int s = blockIdx.y;          // slab b*2+kv
    int b = s >> 1, kv = s & 1;
    int ks = blockIdx.z;
    const bf16* Ah = g_weh + ks * 1024;
    const bf16* Al = g_wel + ks * 1024;
    const bf16* Bh = g_kvh + (size_t)b * N_ * 1024 + (size_t)ks * 1024 * 1024 + kv * 512 + n0;
    const bf16* Bl = g_kvl + (size_t)b * N_ * 1024 + (size_t)ks * 1024 * 1024 + kv * 512 + n0;

    auto PF = [&](int kc, int st) {
        int k0 = kc << 4;
        uint32_t ah = smem_u32(sAh[st]), al = smem_u32(sAl[st]);
        uint32_t bhs = smem_u32(sBh[st]), bls = smem_u32(sBl[st]);
        {
            int row = tid >> 1, q = tid & 1;
            size_t o = (size_t)row * N_ + k0 + q * 8;
            int so = row * RM_STR + q * 8;
            cpasync16(ah + so * 2, Ah + o);
            cpasync16(al + so * 2, Al + o);
        }
#pragma unroll
        for (int u = 0; u < 2; u++) {
            int idx = u * 128 + tid;
            int kr = idx >> 4, q = idx & 15;
            size_t o = (size_t)(k0 + kr) * 1024 + q * 8;
            int so = kr * KM128 + q * 8;
            cpasync16(bhs + so * 2, Bh + o);
            cpasync16(bls + so * 2, Bl + o);
        }
        CPCOMMIT();
    };

    wmma::fragment<wmma::accumulator, 16, 16, 16, float> acc[4][2];
#pragma unroll
    for (int i = 0; i < 4; i++)
#pragma unroll
        for (int j = 0; j < 2; j++) wmma::fill_fragment(acc[i][j], 0.0f);

    PF(0, 0);
    for (int kt = 0; kt < 64; kt++) {    // K=1024
        int st = kt & 1;
        if (kt + 1 < 64) { PF(kt + 1, st ^ 1); CPWAIT(1); }
        else             { CPWAIT(0); }
        __syncthreads();
        wmma::fragment<wmma::matrix_a, 16, 16, 16, bf16, wmma::row_major> ah[4], al[4];
        wmma::fragment<wmma::matrix_b, 16, 16, 16, bf16, wmma::row_major> bh[2], bl[2];
#pragma unroll
        for (int i = 0; i < 4; i++) {
            wmma::load_matrix_sync(ah[i], sAh[st] + i * 16 * RM_STR, RM_STR);
            wmma::load_matrix_sync(al[i], sAl[st] + i * 16 * RM_STR, RM_STR);
        }
#pragma unroll
        for (int j = 0; j < 2; j++) {
            int n = wn * 32 + j * 16;
            wmma::load_matrix_sync(bh[j], sBh[st] + n, KM128);
            wmma::load_matrix_sync(bl[j], sBl[st] + n, KM128);
        }
#pragma unroll
        for (int i = 0; i < 4; i++)
#pragma unroll
            for (int j = 0; j < 2; j++) {
                wmma::mma_sync(acc[i][j], ah[i], bh[j], acc[i][j]);
                wmma::mma_sync(acc[i][j], ah[i], bl[j], acc[i][j]);
                wmma::mma_sync(acc[i][j], al[i], bh[j], acc[i][j]);
            }
        __syncthreads();
    }
    float* Cp = g_projP + (((size_t)ks * 16 + s) * 64) * 512 + n0;
#pragma unroll
    for (int i = 0; i < 4; i++)
#pragma unroll
        for (int j = 0; j < 2; j++)
            wmma::store_matrix_sync(Cp + (size_t)(i * 16) * 512 + wn * 32 + j * 16,
                                    acc[i][j], 512, wmma::mem_row_major);
}

// ================= K3b: reduce proj partials + b_e -> g_kp/g_vp ================
__global__ __launch_bounds__(256) void k_proj_red(const float* __restrict__ b_e) {
    int s = blockIdx.y;
    int e0 = (blockIdx.x * 256 + threadIdx.x) * 4;
    int p = e0 >> 9, d = e0 & 511;
    float4 acc = make_float4(0.f, 0.f, 0.f, 0.f);
#pragma unroll
    for (int ks = 0; ks < 4; ks++) {
        float4 v = *(const float4*)(g_projP + (((size_t)ks * 16 + s) * 64 + p) * 512 + d);
        acc.x += v.x; acc.y += v.y; acc.z += v.z; acc.w += v.w;
    }
    float be = b_e[p];
    acc.x += be; acc.y += be; acc.z += be; acc.w += be;
    int b = s >> 1, kv = s & 1, h = d >> 6, dd = d & 63;
    float* dst = (kv ? g_vp : g_kp) + (((size_t)(b * 8 + h) * 64 + p) * 64 + dd);
    *(float4*)dst = acc;
}

// ================= conversions (destinations referenced in DEVICE code) =====
__device__ __forceinline__ void split4_to(const float* __restrict__ s,
                                          bf16* __restrict__ h,
                                          bf16* __restrict__ l, size_t i) {
    float4 v = *(const float4*)(s + i);
    bf16 hh[4], ll[4];
    split_bf16(v.x, hh[0], ll[0]); split_bf16(v.y, hh[1], ll[1]);
    split_bf16(v.z, hh[2], ll[2]); split_bf16(v.w, hh[3], ll[3]);
    *(uint2*)(h + i) = *(uint2*)hh;
    *(uint2*)(l + i) = *(uint2*)ll;
}

__global__ void c_split_x(const float* __restrict__ s) {
    size_t i = ((size_t)blockIdx.x * 256 + threadIdx.x) * 4;
    split4_to(s, g_xh, g_xl, i);
}
// merged weight conversions: wq (768 blocks) | wo1 (128) | we (256)
__global__ void c_split_w(const float* __restrict__ wq,
                          const float* __restrict__ wo1,
                          const float* __restrict__ we) {
    int blk = blockIdx.x;
    if (blk < 768) {
        size_t i = ((size_t)blk * 256 + threadIdx.x) * 4;
        split4_to(wq, g_wqh, g_wql, i);
    } else if (blk < 896) {
        size_t i = ((size_t)(blk - 768) * 256 + threadIdx.x) * 4;
        split4_to(wo1, g_wo1h, g_wo1l, i);
    } else {
        size_t i = ((size_t)(blk - 896) * 256 + threadIdx.x) * 4;
        split4_to(we, g_weh, g_wel, i);
    }
}

// ================= K2a: qnorm partial sums (grid 64 x 8) =================
__global__ __launch_bounds__(256) void k_qnorm_p() {
    int bh = blockIdx.x, sl = blockIdx.y;
    int b = bh >> 3, h = bh & 7;
    int tid = threadIdx.x;
    int rg = tid >> 4;
    int q4 = tid & 15;
    const float* base = g_qkv + (size_t)b * (N_ * 1536) + h * 64 + q4 * 4;
    int nbeg = sl * 512;
    float4 s = make_float4(0.f, 0.f, 0.f, 0.f);
    for (int n = nbeg + rg; n < nbeg + 512; n += 16) {
        float4 v = *(const float4*)(base + (size_t)n * 1536);
        s.x += v.x * v.x; s.y += v.y * v.y; s.z += v.z * v.z; s.w += v.w * v.w;
    }
    __shared__ float4 red[16][16];
    red[rg][q4] = s;
    __syncthreads();
    if (tid < 16) {
        float4 tot = red[0][tid];
#pragma unroll
        for (int r = 1; r < 16; r++) {
            float4 v = red[r][tid];
            tot.x += v.x; tot.y += v.y; tot.z += v.z; tot.w += v.w;
        }
        *(float4*)&g_qsum[((size_t)bh * 8 + sl) * 64 + tid * 4] = tot;
    }
}

// ================= K2b: qnorm finalize =================
__global__ __launch_bounds__(256) void k_qnorm_f() {
    int idx = blockIdx.x * 256 + threadIdx.x;   // 0..4095
    int bh = idx >> 6, d = idx & 63;
    float tot = 0.f;
#pragma unroll
    for (int sl = 0; sl < 8; sl++) tot += g_qsum[((size_t)bh * 8 + sl) * 64 + d];
    g_qinv[bh * 64 + d] = 1.f / fmaxf(sqrtf(tot), 1e-12f);
}

// ================= K5: row softmax of (gram+gram2) * temperature =============
__global__ __launch_bounds__(256) void k_softmax512(const float* __restrict__ temp) {
    int row = blockIdx.x;
    float t = temp[0];
    float* p = g_gram + (size_t)row * 512;
    const float* p2 = g_gram2 + (size_t)row * 512;
    int tid = threadIdx.x;
    __shared__ float red[256];
    float v0 = (p[tid] + p2[tid]) * t;
    float v1 = (p[tid + 256] + p2[tid + 256]) * t;
    red[tid] = fmaxf(v0, v1);
    __syncthreads();
    for (int s = 128; s > 0; s >>= 1) {
        if (tid < s) red[tid] = fmaxf(red[tid], red[tid + s]);
        __syncthreads();
    }
    float mx = red[0];
    __syncthreads();
    float e0 = __expf(v0 - mx), e1 = __expf(v1 - mx);
    red[tid] = e0 + e1;
    __syncthreads();
    for (int s = 128; s > 0; s >>= 1) {
        if (tid < s) red[tid] += red[tid + s];
        __syncthreads();
    }
    float inv = 1.f / red[0];
    p[tid] = e0 * inv;
    p[tid + 256] = e1 * inv;
}

// ================= K6: fused spatial attention (writes bf16 hi/lo) =================
__global__ __launch_bounds__(128) void k_sa(const float* __restrict__ temp2) {
    __shared__ float kp_s[P_ * D_];
    __shared__ float vp_s[P_ * D_];
    __shared__ float qi_s[D_];
    int bh = blockIdx.y;
    int b = bh >> 3, h = bh & 7;
    int n = blockIdx.x * 128 + threadIdx.x;
    const float4* kp4 = (const float4*)(g_kp + bh * (P_ * D_));
    const float4* vp4 = (const float4*)(g_vp + bh * (P_ * D_));
    for (int i = threadIdx.x; i < (P_ * D_) / 4; i += 128) {
        ((float4*)kp_s)[i] = kp4[i];
        ((float4*)vp_s)[i] = vp4[i];
    }
    if (threadIdx.x < 64) qi_s[threadIdx.x] = g_qinv[bh * 64 + threadIdx.x];
    __syncthreads();
    float t2 = temp2[h];
    const float* qrow = g_qkv + (size_t)b * (N_ * 1536) + (size_t)n * 1536 + h * 64;

    float q[64];
#pragma unroll
    for (int d = 0; d < 64; d++) q[d] = qrow[d] * qi_s[d];

    float s[64];
    float mx = -1e30f;
#pragma unroll
    for (int p = 0; p < 64; p++) {
        float acc = 0.f;
#pragma unroll
        for (int d = 0; d < 64; d += 4) {
            float4 k4 = *(const float4*)&kp_s[p * 64 + d];
            acc += q[d] * k4.x + q[d + 1] * k4.y + q[d + 2] * k4.z + q[d + 3] * k4.w;
        }
        s[p] = acc * t2;
        mx = fmaxf(mx, s[p]);
    }
    float sum = 0.f;
#pragma unroll
    for (int p = 0; p < 64; p++) {
        s[p] = __expf(s[p] - mx);
        sum += s[p];
    }
    float inv = 1.f / sum;

    float o[64];
#pragma unroll
    for (int d = 0; d < 64; d++) o[d] = 0.f;
#pragma unroll
    for (int p = 0; p < 64; p++) {
        float sp = s[p] * inv;
#pragma unroll
        for (int d = 0; d < 64; d += 4) {
            float4 v4 = *(const float4*)&vp_s[p * 64 + d];
            o[d] += sp * v4.x;
            o[d + 1] += sp * v4.y;
            o[d + 2] += sp * v4.z;
            o[d + 3] += sp * v4.w;
        }
    }
    int rbase = h * 8 + (n >> 9);
    int col = n & 511;
    size_t boff = (size_t)b * (N_ * C_);
#pragma unroll
    for (int d = 0; d < 64; d++) {
        bf16 hh, ll;
        split_bf16(o[d], hh, ll);
        size_t idx = boff + (size_t)(d * 64 + rbase) * 512 + col;
        g_xsah[idx] = hh;
        g_xsal[idx] = ll;
    }
}

// ================= K7: M^T[b,j,k] = (attn^T @ w_o2^T)^T, bf16 hi/lo out =================
#define SP2 132
__device__ __forceinline__ void gemmM(
    const float* __restrict__ A, int lda, const float* __restrict__ B, int ldb,
    int K, float (&acc)[8][8], float (*As)[8][SP2], float (*Bs)[8][SP2]) {
    int tid = threadIdx.x;
    int tx = tid & 15, ty = tid >> 4;
    int rowT = tid >> 1, kqT = (tid & 1) * 4;
    int krD = tid >> 5, mqD = (tid & 31) * 4;
    float4 ra, rb;
    auto loadA = [&](int k0) { ra = *(const float4*)&A[(size_t)(k0 + krD) * lda + mqD]; };
    auto loadB = [&](int k0) { rb = *(const float4*)&B[(size_t)rowT * ldb + k0 + kqT]; };
    auto storeA = [&](int buf) { *(float4*)&As[buf][krD][mqD] = ra; };
    auto storeB = [&](int buf) {
        Bs[buf][kqT + 0][rowT] = rb.x; Bs[buf][kqT + 1][rowT] = rb.y;
        Bs[buf][kqT + 2][rowT] = rb.z; Bs[buf][kqT + 3][rowT] = rb.w;
    };
    loadA(0); loadB(0); storeA(0); storeB(0);
    __syncthreads();
    int nk = K >> 3;
    for (int kt = 0; kt < nk; kt++) {
        int cur = kt & 1;
        if (kt + 1 < nk) { loadA((kt + 1) << 3); loadB((kt + 1) << 3); }
#pragma unroll
        for (int kk = 0; kk < 8; kk++) {
            float4 a0 = *(const float4*)&As[cur][kk][ty * 8];
            float4 a1 = *(const float4*)&As[cur][kk][ty * 8 + 4];
            float4 b0 = *(const float4*)&Bs[cur][kk][tx * 8];
            float4 b1 = *(const float4*)&Bs[cur][kk][tx * 8 + 4];
            float a[8] = {a0.x, a0.y, a0.z, a0.w, a1.x, a1.y, a1.z, a1.w};
            float b[8] = {b0.x, b0.y, b0.z, b0.w, b1.x, b1.y, b1.z, b1.w};
#pragma unroll
            for (int i = 0; i < 8; i++)
#pragma unroll
                for (int j = 0; j < 8; j++) acc[i][j] += a[i] * b[j];
        }
        if (kt + 1 < nk) { storeA(cur ^ 1); storeB(cur ^ 1); __syncthreads(); }
    }
}

__global__ __launch_bounds__(256) void k_M(const float* __restrict__ w_o2) {
    __shared__ float As[2][8][SP2];
    __shared__ float Bs[2][8][SP2];
    int b = blockIdx.z;
    int m0 = blockIdx.y * 128;
    int n0 = blockIdx.x * 128;
    const float* A = g_gram + (size_t)b * (512 * 512);
    float acc[8][8] = {};
    gemmM(A + m0, 512, w_o2 + (size_t)n0 * 512, 512, 512, acc, As, Bs);
    int tx = threadIdx.x & 15, ty = threadIdx.x >> 4;
#pragma unroll
    for (int i = 0; i < 8; i++) {
        int k = m0 + ty * 8 + i;
#pragma unroll
        for (int jj = 0; jj < 8; jj++) {
            int j = n0 + tx * 8 + jj;
            bf16 hh, ll;
            split_bf16(acc[i][jj], hh, ll);
            size_t idx = ((size_t)b * 256 + j) * 512 + k;
            g_Mh[idx] = hh;
            g_Ml[idx] = ll;
        }
    }
}

// ================= launch =================
extern "C" void kernel_launch(void* const* d_in, const int* in_sizes, int n_in,
                              void* d_out, int out_size) {
    const float* x      = (const float*)d_in[0];
    const float* w_qkv  = (const float*)d_in[1];
    const float* w_e    = (const float*)d_in[2];
    const float* b_e    = (const float*)d_in[3];
    const float* temp   = (const float*)d_in[4];
    const float* temp2  = (const float*)d_in[5];
    const float* w_o1   = (const float*)d_in[6];
    const float* b_o1   = (const float*)d_in[7];
    const float* w_o2   = (const float*)d_in[8];
    const float* b_o2   = (const float*)d_in[9];
    float* out = (float*)d_out;

    // bf16 hi/lo conversions (globals referenced inside kernels only)
    c_split_x<<<(B_ * N_ * C_) / 1024, 256>>>(x);
    c_split_w<<<768 + 128 + 256, 256>>>(w_qkv, w_o1, w_e);

    k_qkv_w<<<dim3(12, 256), 256>>>();            // q->fp32, K/V->bf16 split
    k_qnorm_p<<<dim3(64, 8), 256>>>();            // parallel partials
    k_qnorm_f<<<16, 256>>>();
    k_proj_n<<<dim3(4, 16, 4), 128>>>();          // split-K=4 partials
    k_proj_red<<<dim3(32, 16), 256>>>(b_e);
    k_gram_w<<<dim3(4, 4, 16), 256>>>();          // split-K=2
    k_softmax512<<<B_ * C_, 256>>>(temp);
    k_sa<<<dim3(32, 64), 128>>>(temp2);
    k_M<<<dim3(2, 4, 8), 256>>>(w_o2);
    k_out_w<<<dim3(2, 256, 2), 256>>>(b_o1, b_o2, out);  // fused bias epilogue
}